// round 6
// baseline (speedup 1.0000x reference)
#include <cuda_runtime.h>
#include <cstdint>

#define T_STEPS 256
#define NEG (-1.0e10f)
#define HALF_LOG2PI 0.9189385332046727f
typedef unsigned long long u64;

extern __shared__ char dynsm[];   // single dynamic-smem symbol for all kernels

// ---------------- global scratch ----------------
__device__ float g_arwin[2048 * 96];
__device__ float g_w0p[256 * 96];
__device__ float g_pre[2048 * 256];
__device__ float g_gih[2048 * 2048];
__device__ float g_base[1024 * 256];
__device__ float g_hall[2048 * 512];
__device__ float g_hpart[2048 * 256];   // also p0 scratch
__device__ float g_hbuf[8192];
__device__ float g_em[2048 * 128];
__device__ float g_tv[2048 * 128];
__device__ u64 g_ow1p[8 * 32 * 128];    // pre-packed ow1 col-pairs, per 32-k chunk
__device__ u64 g_ow2p[8 * 32 * 96];     // pre-packed ow2
__device__ unsigned g_cnt;
__device__ unsigned g_gen;

// ---------------- helpers ----------------
__device__ __forceinline__ u64 pkxy(float x, float y) {
    u64 r; asm("mov.b64 %0, {%1, %2};" : "=l"(r) : "f"(x), "f"(y)); return r;
}
__device__ __forceinline__ void fma2(u64& d, u64 a, u64 b) {
    asm("fma.rn.f32x2 %0, %1, %2, %0;" : "+l"(d) : "l"(a), "l"(b));
}
__device__ __forceinline__ float2 up2(u64 v) {
    float2 f; asm("mov.b64 {%0, %1}, %2;" : "=f"(f.x), "=f"(f.y) : "l"(v)); return f;
}
__device__ __forceinline__ void sts_dup(unsigned addr, float v) {
    asm volatile("st.shared.v2.b32 [%0], {%1, %1};" :: "r"(addr), "f"(v));
}
__device__ __forceinline__ float sigm(float x) { return 1.f / (1.f + expf(-x)); }

// epoch grid barrier: monotonic counter, release/acquire, no fences
__device__ __forceinline__ void gbar_ep(unsigned target) {
    __syncthreads();
    if (threadIdx.x == 0) {
        unsigned old;
        asm volatile("atom.release.gpu.global.add.u32 %0, [%1], %2;"
                     : "=r"(old) : "l"(&g_cnt), "r"(1u) : "memory");
        if (old + 1u == target) {
            asm volatile("st.release.gpu.global.u32 [%0], %1;"
                         :: "l"(&g_gen), "r"(target) : "memory");
        } else {
            unsigned cur;
            do {
                asm volatile("ld.acquire.gpu.global.u32 %0, [%1];"
                             : "=r"(cur) : "l"(&g_gen) : "memory");
            } while (cur < target);
        }
    }
    __syncthreads();
}

// ---------------- k_prep: pads + pre-packs + barrier reset ----------------
__global__ __launch_bounds__(256) void k_prep(const float* __restrict__ mels,
                                              const float* __restrict__ w0,
                                              const float* __restrict__ ow1,
                                              const float* __restrict__ ow2) {
    int i0 = blockIdx.x * 256 + threadIdx.x;
    int stride = gridDim.x * 256;
    if (i0 == 0) { g_cnt = 0; g_gen = 0; }
    for (int e = i0; e < 2048 * 96; e += stride) {
        int r = e / 96, k = e - r * 96;
        int t = r >> 3, b = r & 7;
        g_arwin[e] = (k < 80 && t > 0) ? mels[((size_t)b * 80 + k) * 256 + t - 1] : 0.f;
    }
    for (int e = i0; e < 256 * 96; e += stride) {
        int c = e / 96, k = e - c * 96;
        g_w0p[e] = (k < 80) ? w0[c * 80 + k] : 0.f;
    }
    for (int e = i0; e < 32768; e += stride) {   // ow1 pack
        int ch = e >> 12, rem = e & 4095, kk = rem >> 7, p = rem & 127;
        int ca = (p & 31) + 64 * (p >> 5), cb = ca + 32;
        int k = ch * 32 + kk;
        g_ow1p[e] = pkxy(ow1[ca * 256 + k], ow1[cb * 256 + k]);
    }
    for (int e = i0; e < 24576; e += stride) {   // ow2 pack (clamped to col 160)
        int ch = e / 3072, rem = e - ch * 3072, kk = rem / 96, p = rem - kk * 96;
        int ca = (p & 31) + 64 * (p >> 5), cb = ca + 32;
        if (ca > 160) ca = 160;
        if (cb > 160) cb = 160;
        int k = ch * 32 + kk;
        g_ow2p[e] = pkxy(ow2[ca * 256 + k], ow2[cb * 256 + k]);
    }
}

// ---------------- generic GEMM: 64x256 tile, 512 thr, dup-A f32x2 ----------------
// dyn smem: Ad[32][64] u64 (16384B) + Bs[32][128] u64 (32768B) = 49152B
__global__ __launch_bounds__(512) void k_gemm(
    const float* __restrict__ A, int lda, int K,
    const float* __restrict__ W, int ldw, int wmax,
    const float* __restrict__ b1, const float* __restrict__ b2,
    float* __restrict__ C, int ldc, int relu) {
    u64* Ad = (u64*)dynsm;
    u64* Bs = (u64*)(dynsm + 16384);
    unsigned ad_base = (unsigned)__cvta_generic_to_shared(Ad);
    int tid = threadIdx.x, w = tid >> 5, lane = tid & 31;
    int r0 = blockIdx.x * 64, c0 = blockIdx.y * 256;
    u64 acc[16];
#pragma unroll
    for (int i = 0; i < 16; ++i) acc[i] = 0ull;
    int ar = tid & 63, kq = (tid >> 6) * 4;
    const float* Arow = A + (size_t)(r0 + ar) * lda + kq;
    int bp = tid & 127, kg = (tid >> 7) * 8;
    int ca = c0 + (bp & 31) + 64 * (bp >> 5);
    int cb = ca + 32;
    if (ca > wmax) ca = wmax;
    if (cb > wmax) cb = wmax;
    const float* wa = W + (size_t)ca * ldw + kg;
    const float* wb = W + (size_t)cb * ldw + kg;

    for (int k0 = 0; k0 < K; k0 += 32) {
        __syncthreads();
        {   // build duplicated A
            float4 v = *(const float4*)(Arow + k0);
            unsigned a0 = ad_base + (kq * 64 + ar) * 8;
            sts_dup(a0, v.x);
            sts_dup(a0 + 512, v.y);
            sts_dup(a0 + 1024, v.z);
            sts_dup(a0 + 1536, v.w);
        }
        {   // pack B col-pairs
            float4 va0 = *(const float4*)(wa + k0);
            float4 va1 = *(const float4*)(wa + k0 + 4);
            float4 vb0 = *(const float4*)(wb + k0);
            float4 vb1 = *(const float4*)(wb + k0 + 4);
            u64* dst = Bs + kg * 128 + bp;
            dst[0 * 128] = pkxy(va0.x, vb0.x); dst[1 * 128] = pkxy(va0.y, vb0.y);
            dst[2 * 128] = pkxy(va0.z, vb0.z); dst[3 * 128] = pkxy(va0.w, vb0.w);
            dst[4 * 128] = pkxy(va1.x, vb1.x); dst[5 * 128] = pkxy(va1.y, vb1.y);
            dst[6 * 128] = pkxy(va1.z, vb1.z); dst[7 * 128] = pkxy(va1.w, vb1.w);
        }
        __syncthreads();
#pragma unroll 4
        for (int kk = 0; kk < 32; ++kk) {
            ulonglong2 aA = *(const ulonglong2*)&Ad[kk * 64 + w * 4];
            ulonglong2 aB = *(const ulonglong2*)&Ad[kk * 64 + w * 4 + 2];
            const u64* br = Bs + kk * 128 + lane;
            u64 b0 = br[0], b1 = br[32], b2 = br[64], b3 = br[96];
            fma2(acc[0], aA.x, b0); fma2(acc[1], aA.x, b1); fma2(acc[2], aA.x, b2); fma2(acc[3], aA.x, b3);
            fma2(acc[4], aA.y, b0); fma2(acc[5], aA.y, b1); fma2(acc[6], aA.y, b2); fma2(acc[7], aA.y, b3);
            fma2(acc[8], aB.x, b0); fma2(acc[9], aB.x, b1); fma2(acc[10], aB.x, b2); fma2(acc[11], aB.x, b3);
            fma2(acc[12], aB.y, b0); fma2(acc[13], aB.y, b1); fma2(acc[14], aB.y, b2); fma2(acc[15], aB.y, b3);
        }
    }
    float bxa[4], bxb[4];
#pragma unroll
    for (int j = 0; j < 4; ++j) {
        int c = c0 + lane + 64 * j;
        bxa[j] = (b1 ? b1[c] : 0.f) + (b2 ? b2[c] : 0.f);
        bxb[j] = (b1 ? b1[c + 32] : 0.f) + (b2 ? b2[c + 32] : 0.f);
    }
#pragma unroll
    for (int i = 0; i < 4; ++i) {
        float* cr = C + (size_t)(r0 + w * 4 + i) * ldc + c0;
#pragma unroll
        for (int j = 0; j < 4; ++j) {
            float2 v = up2(acc[i * 4 + j]);
            float x = v.x + bxa[j], y = v.y + bxb[j];
            if (relu) { x = fmaxf(x, 0.f); y = fmaxf(y, 0.f); }
            cr[lane + 64 * j] = x;
            cr[lane + 64 * j + 32] = y;
        }
    }
}

// ---------------- k_scan: LSTM recurrence, 64 CTAs, weights resident ----------------
#define SCAN_SMEM ((32 + 8) * 516 * 4)
__global__ __launch_bounds__(256) void k_scan(const float* __restrict__ whh) {
    float* wsm = (float*)dynsm;
    float* hs = (float*)dynsm + 32 * 516;
    int tid = threadIdx.x, cta = blockIdx.x;
    int mbase = cta * 8;
    {
        int rowid = tid >> 3, seg = tid & 7;
        int g = rowid & 3, ml = rowid >> 2;
        const float* src = whh + (size_t)(g * 512 + mbase + ml) * 512 + seg * 64;
        float* dst = wsm + rowid * 516 + seg * 64;
#pragma unroll
        for (int q = 0; q < 64; q += 4) *(float4*)(dst + q) = *(const float4*)(src + q);
    }
    int gt = cta * 256 + tid;
    if (gt < 8192) g_hbuf[gt] = 0.f;

    int b = tid & 7, gate = (tid >> 3) & 3, ml = tid >> 5;
    int m = mbase + ml;
    float cst = 0.f;
    unsigned epoch = 1;
    gbar_ep(epoch * 64);

    int cur = 0;
    for (int t = 0; t < T_STEPS; ++t) {
        float gihv0 = 0.f, gihv1 = 0.f, gihv2 = 0.f, gihv3 = 0.f;
        if (gate == 0) {
            const float* gp = g_gih + ((size_t)t * 8 + b) * 2048 + m;
            gihv0 = __ldg(gp); gihv1 = __ldg(gp + 512);
            gihv2 = __ldg(gp + 1024); gihv3 = __ldg(gp + 1536);
        }
        {
            int bb = tid >> 5, k0 = (tid & 31) * 16;
            const float4* src = (const float4*)(g_hbuf + cur * 4096 + bb * 512 + k0);
            float* dst = hs + bb * 516 + k0;
#pragma unroll
            for (int q = 0; q < 4; ++q) *(float4*)(dst + q * 4) = __ldcg(src + q);
        }
        __syncthreads();
        u64 acc = 0ull;
        const float* wr = wsm + (ml * 4 + gate) * 516;
        const float* hr = hs + b * 516;
#pragma unroll 8
        for (int k = 0; k < 512; k += 8) {
            ulonglong2 wa = *(const ulonglong2*)(wr + k);
            ulonglong2 wb = *(const ulonglong2*)(wr + k + 4);
            ulonglong2 ha = *(const ulonglong2*)(hr + k);
            ulonglong2 hb = *(const ulonglong2*)(hr + k + 4);
            fma2(acc, wa.x, ha.x); fma2(acc, wa.y, ha.y);
            fma2(acc, wb.x, hb.x); fma2(acc, wb.y, hb.y);
        }
        float2 dv = up2(acc);
        float dot = dv.x + dv.y;
        int lb = tid & 7;
        float d0 = __shfl_sync(0xffffffffu, dot, lb + 0);
        float d1 = __shfl_sync(0xffffffffu, dot, lb + 8);
        float d2 = __shfl_sync(0xffffffffu, dot, lb + 16);
        float d3 = __shfl_sync(0xffffffffu, dot, lb + 24);
        if (gate == 0) {
            float gi = gihv0 + d0, gf = gihv1 + d1, gg = gihv2 + d2, go = gihv3 + d3;
            float cn = sigm(gf) * cst + sigm(gi) * tanhf(gg);
            float hn = sigm(go) * tanhf(cn);
            cst = cn;
            __stcg(&g_hbuf[(cur ^ 1) * 4096 + b * 512 + m], hn);
            g_hall[((size_t)t * 8 + b) * 512 + m] = hn;
        }
        cur ^= 1;
        epoch++;
        gbar_ep(epoch * 64);
    }
}

// ---------------- k_big: fused obs-net + emission ----------------
// 512 thr, tile 64 rows x 256 cols. smem: a2s[64][260] + Ad[32][64]u64 + Bs[32][128]u64
#define BIG_SMEM (66560 + 16384 + 32768)
__global__ __launch_bounds__(512) void k_big(
    const float* __restrict__ mels, const float* __restrict__ ob1,
    const float* __restrict__ ob2, const int* __restrict__ inputs_len) {
    float* a2s = (float*)dynsm;                 // [64][260]
    u64* Ad = (u64*)(dynsm + 66560);            // [32][64]
    u64* Bs = (u64*)(dynsm + 66560 + 16384);    // [32][128] (stage2 uses [32][96])
    __shared__ float xs[80];
    __shared__ int ilen_s;
    unsigned ad_base = (unsigned)__cvta_generic_to_shared(Ad);
    int tid = threadIdx.x, w = tid >> 5, lane = tid & 31;
    int bid = blockIdx.x;
    int t = bid >> 4, rt = bid & 15;
    int r0 = rt * 64;
    int b = r0 >> 7, n0 = r0 & 127;

    if (tid < 80) xs[tid] = mels[((size_t)b * 80 + tid) * 256 + t];
    if (tid == 80) ilen_s = inputs_len[b];

    int ar = tid & 63, kq = (tid >> 6) * 4;
    const float* bp_ = g_base + (size_t)(r0 + ar) * 256 + kq;
    const float* hp_ = g_hpart + ((size_t)t * 8 + b) * 256 + kq;

    // ---- stage 1: a2 = relu(a1 @ ow1^T + ob1) ----
    u64 acc[16];
#pragma unroll
    for (int i = 0; i < 16; ++i) acc[i] = 0ull;
    for (int ch = 0; ch < 8; ++ch) {
        int k0 = ch * 32;
        __syncthreads();
        {   // build duplicated a1 = relu(base + hpart)
            float4 bv = *(const float4*)(bp_ + k0);
            float4 hv = *(const float4*)(hp_ + k0);
            unsigned a0 = ad_base + (kq * 64 + ar) * 8;
            sts_dup(a0, fmaxf(bv.x + hv.x, 0.f));
            sts_dup(a0 + 512, fmaxf(bv.y + hv.y, 0.f));
            sts_dup(a0 + 1024, fmaxf(bv.z + hv.z, 0.f));
            sts_dup(a0 + 1536, fmaxf(bv.w + hv.w, 0.f));
        }
        {   // copy pre-packed ow1 chunk (4096 u64)
            const u64* src = g_ow1p + ch * 4096 + tid * 8;
            u64* dst = Bs + tid * 8;
            ulonglong2 v0 = *(const ulonglong2*)(src);
            ulonglong2 v1 = *(const ulonglong2*)(src + 2);
            ulonglong2 v2 = *(const ulonglong2*)(src + 4);
            ulonglong2 v3 = *(const ulonglong2*)(src + 6);
            *(ulonglong2*)(dst) = v0; *(ulonglong2*)(dst + 2) = v1;
            *(ulonglong2*)(dst + 4) = v2; *(ulonglong2*)(dst + 6) = v3;
        }
        __syncthreads();
#pragma unroll 4
        for (int kk = 0; kk < 32; ++kk) {
            ulonglong2 aA = *(const ulonglong2*)&Ad[kk * 64 + w * 4];
            ulonglong2 aB = *(const ulonglong2*)&Ad[kk * 64 + w * 4 + 2];
            const u64* br = Bs + kk * 128 + lane;
            u64 b0 = br[0], b1 = br[32], b2 = br[64], b3 = br[96];
            fma2(acc[0], aA.x, b0); fma2(acc[1], aA.x, b1); fma2(acc[2], aA.x, b2); fma2(acc[3], aA.x, b3);
            fma2(acc[4], aA.y, b0); fma2(acc[5], aA.y, b1); fma2(acc[6], aA.y, b2); fma2(acc[7], aA.y, b3);
            fma2(acc[8], aB.x, b0); fma2(acc[9], aB.x, b1); fma2(acc[10], aB.x, b2); fma2(acc[11], aB.x, b3);
            fma2(acc[12], aB.y, b0); fma2(acc[13], aB.y, b1); fma2(acc[14], aB.y, b2); fma2(acc[15], aB.y, b3);
        }
    }
    __syncthreads();
    {   // write a2 row-major into a2s
        float o1a[4], o1b[4];
#pragma unroll
        for (int j = 0; j < 4; ++j) {
            o1a[j] = ob1[lane + 64 * j];
            o1b[j] = ob1[lane + 64 * j + 32];
        }
#pragma unroll
        for (int i = 0; i < 4; ++i) {
            float* row = a2s + (w * 4 + i) * 260;
#pragma unroll
            for (int j = 0; j < 4; ++j) {
                float2 v = up2(acc[i * 4 + j]);
                row[lane + 64 * j] = fmaxf(v.x + o1a[j], 0.f);
                row[lane + 64 * j + 32] = fmaxf(v.y + o1b[j], 0.f);
            }
        }
    }
    // ---- stage 2: p = a2 @ ow2^T + ob2 (161 cols via 192) ----
    u64 acc2[12];
#pragma unroll
    for (int i = 0; i < 12; ++i) acc2[i] = 0ull;
    for (int ch = 0; ch < 8; ++ch) {
        int k0 = ch * 32;
        __syncthreads();
        {   // build duplicated a2
            float4 av = *(const float4*)&a2s[ar * 260 + k0 + kq];
            unsigned a0 = ad_base + (kq * 64 + ar) * 8;
            sts_dup(a0, av.x);
            sts_dup(a0 + 512, av.y);
            sts_dup(a0 + 1024, av.z);
            sts_dup(a0 + 1536, av.w);
        }
        {   // copy pre-packed ow2 chunk (3072 u64)
            const u64* src = g_ow2p + ch * 3072 + tid * 6;
            u64* dst = Bs + tid * 6;
            ulonglong2 v0 = *(const ulonglong2*)(src);
            ulonglong2 v1 = *(const ulonglong2*)(src + 2);
            ulonglong2 v2 = *(const ulonglong2*)(src + 4);
            *(ulonglong2*)(dst) = v0; *(ulonglong2*)(dst + 2) = v1;
            *(ulonglong2*)(dst + 4) = v2;
        }
        __syncthreads();
#pragma unroll 4
        for (int kk = 0; kk < 32; ++kk) {
            ulonglong2 aA = *(const ulonglong2*)&Ad[kk * 64 + w * 4];
            ulonglong2 aB = *(const ulonglong2*)&Ad[kk * 64 + w * 4 + 2];
            const u64* br = Bs + kk * 96 + lane;
            u64 b0 = br[0], b1 = br[32], b2 = br[64];
            fma2(acc2[0], aA.x, b0); fma2(acc2[1], aA.x, b1); fma2(acc2[2], aA.x, b2);
            fma2(acc2[3], aA.y, b0); fma2(acc2[4], aA.y, b1); fma2(acc2[5], aA.y, b2);
            fma2(acc2[6], aB.x, b0); fma2(acc2[7], aB.x, b1); fma2(acc2[8], aB.x, b2);
            fma2(acc2[9], aB.y, b0); fma2(acc2[10], aB.y, b1); fma2(acc2[11], aB.y, b2);
        }
    }
    __syncthreads();
    float* ps = a2s;   // overlay [64][164]
#pragma unroll
    for (int i = 0; i < 4; ++i) {
        int row = w * 4 + i;
#pragma unroll
        for (int j = 0; j < 3; ++j) {
            float2 v = up2(acc2[i * 3 + j]);
            int c = lane + 64 * j;
            if (c < 161) ps[row * 164 + c] = v.x + ob2[c];
            int c2 = c + 32;
            if (c2 < 161) ps[row * 164 + c2] = v.y + ob2[c2];
        }
    }
    __syncthreads();
    {   // emission: warp w -> rows w*4..+4; 8 lanes per row, 10 d's each
        int ri = lane >> 3, part = lane & 7;
        int row = w * 4 + ri;
        const float* pr = ps + row * 164;
        float sum = 0.f;
        int d0 = part * 10;
        for (int d = d0; d < d0 + 10; ++d) {
            float mean = pr[d], sh = pr[80 + d];
            float stdv = fmaxf(sh, 0.f) + log1pf(expf(-fabsf(sh))) + 1e-3f;
            float z = (xs[d] - mean) / stdv;
            sum += -0.5f * z * z - logf(stdv) - HALF_LOG2PI;
        }
        sum += __shfl_xor_sync(0xffffffffu, sum, 1);
        sum += __shfl_xor_sync(0xffffffffu, sum, 2);
        sum += __shfl_xor_sync(0xffffffffu, sum, 4);
        if (part == 0) {
            int n = n0 + row;
            g_em[((size_t)t * 8 + b) * 128 + n] = (n < ilen_s) ? sum : 0.f;
            g_tv[((size_t)t * 8 + b) * 128 + n] = pr[160];
        }
    }
}

// ---------------- k_hmm: one warp per batch, shuffle-only ----------------
__global__ __launch_bounds__(32) void k_hmm(
    const int* __restrict__ inputs_len, const int* __restrict__ mel_lens,
    float* __restrict__ out) {
    int b = blockIdx.x, lane = threadIdx.x;
    int ilen = inputs_len[b], mlen = mel_lens[b];
    float la[4];
    float lp = 0.f;
    float* outla = out + 8 + (size_t)b * 256 * 128;
    float emc[4], tvc[4];
#pragma unroll
    for (int q = 0; q < 4; ++q) {
        emc[q] = g_em[(size_t)b * 128 + q * 32 + lane];
        tvc[q] = g_tv[(size_t)b * 128 + q * 32 + lane];
    }
    for (int t = 0; t < T_STEPS; ++t) {
        float emn[4], tvn[4];
        if (t + 1 < T_STEPS) {
#pragma unroll
            for (int q = 0; q < 4; ++q) {
                emn[q] = __ldcg(&g_em[((size_t)(t + 1) * 8 + b) * 128 + q * 32 + lane]);
                tvn[q] = __ldcg(&g_tv[((size_t)(t + 1) * 8 + b) * 128 + q * 32 + lane]);
            }
        }
        float la_t[4];
        if (t == 0) {
#pragma unroll
            for (int q = 0; q < 4; ++q)
                la_t[q] = emc[q] + ((q == 0 && lane == 0) ? 0.f : NEG);
        } else {
            float st_[4], mvv[4];
#pragma unroll
            for (int q = 0; q < 4; ++q) {
                float tv = tvc[q];
                float lstay = logf(fmaxf(1.f / (1.f + expf(tv)), 1e-4f));
                float lmove = logf(fmaxf(1.f / (1.f + expf(-tv)), 1e-4f));
                st_[q] = la[q] + lstay;
                mvv[q] = la[q] + lmove;
            }
            float lv[4];
#pragma unroll
            for (int q = 0; q < 4; ++q)
                lv[q] = __shfl_up_sync(0xffffffffu, mvv[q], 1);
            float c1 = __shfl_sync(0xffffffffu, mvv[0], 31);
            float c2 = __shfl_sync(0xffffffffu, mvv[1], 31);
            float c3 = __shfl_sync(0xffffffffu, mvv[2], 31);
            if (lane == 0) { lv[0] = NEG; lv[1] = c1; lv[2] = c2; lv[3] = c3; }
#pragma unroll
            for (int q = 0; q < 4; ++q) {
                float mx = fmaxf(st_[q], lv[q]);
                float mn = fminf(st_[q], lv[q]);
                float o = mx + log1pf(expf(mn - mx));
                int n = q * 32 + lane;
                o = (n < ilen) ? o : NEG;
                la_t[q] = emc[q] + o;
            }
        }
        // logsumexp over 128 states
        float mx = fmaxf(fmaxf(la_t[0], la_t[1]), fmaxf(la_t[2], la_t[3]));
#pragma unroll
        for (int off = 16; off; off >>= 1)
            mx = fmaxf(mx, __shfl_xor_sync(0xffffffffu, mx, off));
        float s = expf(la_t[0] - mx) + expf(la_t[1] - mx) +
                  expf(la_t[2] - mx) + expf(la_t[3] - mx);
#pragma unroll
        for (int off = 16; off; off >>= 1)
            s += __shfl_xor_sync(0xffffffffu, s, off);
        float log_c = mx + logf(s);
#pragma unroll
        for (int q = 0; q < 4; ++q) {
            la[q] = la_t[q] - log_c;
            outla[(size_t)t * 128 + q * 32 + lane] = la[q];
        }
        if (t < mlen) lp += log_c;
#pragma unroll
        for (int q = 0; q < 4; ++q) { emc[q] = emn[q]; tvc[q] = tvn[q]; }
    }
    if (lane == 0) out[b] = lp;
}

// ---------------- launch ----------------
extern "C" void kernel_launch(void* const* d_in, const int* in_sizes, int n_in,
                              void* d_out, int out_size) {
    const float* inputs = (const float*)d_in[0];
    const float* mels = (const float*)d_in[1];
    const float* pw0 = (const float*)d_in[2];
    const float* pw1 = (const float*)d_in[3];
    const float* wih = (const float*)d_in[4];
    const float* whh = (const float*)d_in[5];
    const float* bih = (const float*)d_in[6];
    const float* bhh = (const float*)d_in[7];
    const float* ow0 = (const float*)d_in[8];
    const float* ob0 = (const float*)d_in[9];
    const float* ow1 = (const float*)d_in[10];
    const float* ob1 = (const float*)d_in[11];
    const float* ow2 = (const float*)d_in[12];
    const float* ob2 = (const float*)d_in[13];
    const int* inputs_len = (const int*)d_in[14];
    const int* mel_lens = (const int*)d_in[15];
    float* out = (float*)d_out;

    cudaFuncSetAttribute(k_scan, cudaFuncAttributeMaxDynamicSharedMemorySize, SCAN_SMEM);
    cudaFuncSetAttribute(k_big, cudaFuncAttributeMaxDynamicSharedMemorySize, BIG_SMEM);
    cudaFuncSetAttribute(k_gemm, cudaFuncAttributeMaxDynamicSharedMemorySize, 49152);

    float *arwin, *w0p, *pre, *base, *hall, *hpart, *gih;
    cudaGetSymbolAddress((void**)&arwin, g_arwin);
    cudaGetSymbolAddress((void**)&w0p, g_w0p);
    cudaGetSymbolAddress((void**)&pre, g_pre);
    cudaGetSymbolAddress((void**)&base, g_base);
    cudaGetSymbolAddress((void**)&hall, g_hall);
    cudaGetSymbolAddress((void**)&hpart, g_hpart);
    cudaGetSymbolAddress((void**)&gih, g_gih);

    k_prep<<<256, 256>>>(mels, pw0, ow1, ow2);
    // p0 = relu(arwin @ w0p^T) -> g_hpart (scratch)
    k_gemm<<<dim3(32, 1), 512, 49152>>>(arwin, 96, 96, w0p, 96, 255, nullptr, nullptr, hpart, 256, 1);
    // pre1 = relu(p0 @ pw1^T) -> g_pre
    k_gemm<<<dim3(32, 1), 512, 49152>>>(hpart, 256, 256, pw1, 256, 255, nullptr, nullptr, pre, 256, 1);
    // gih = pre1 @ wih^T + bih + bhh
    k_gemm<<<dim3(32, 8), 512, 49152>>>(pre, 256, 256, wih, 256, 2047, bih, bhh, gih, 2048, 0);
    // base = inputs @ ow0[:, :512]^T + ob0
    k_gemm<<<dim3(16, 1), 512, 49152>>>(inputs, 512, 512, ow0, 1024, 255, ob0, nullptr, base, 256, 0);
    // LSTM scan
    k_scan<<<64, 256, SCAN_SMEM>>>(whh);
    // hpart = hall @ ow0[:, 512:]^T
    k_gemm<<<dim3(32, 1), 512, 49152>>>(hall, 512, 512, ow0 + 512, 1024, 255, nullptr, nullptr, hpart, 256, 0);
    // fused obs-net + emission
    k_big<<<4096, 512, BIG_SMEM>>>(mels, ob1, ob2, inputs_len);
    // HMM forward
    k_hmm<<<8, 32>>>(inputs_len, mel_lens, out);
}

// round 9
// speedup vs baseline: 1.0591x; 1.0591x over previous
#include <cuda_runtime.h>
#include <cstdint>

#define T_STEPS 256
#define NEG (-1.0e10f)
#define HALF_LOG2PI 0.9189385332046727f
typedef unsigned long long u64;

extern __shared__ char dynsm[];   // single dynamic-smem symbol

// ---------------- global scratch ----------------
__device__ float g_arwin[2048 * 96];
__device__ float g_w0p[256 * 96];
__device__ float g_pre[2048 * 256];
__device__ float g_gih[2048 * 2048];
__device__ float g_base[1024 * 256];
__device__ float g_hall[2048 * 512];
__device__ float g_hpart[2048 * 256];   // also p0 scratch
__device__ float g_hbuf[8192];
__device__ float g_em[2048 * 128];
__device__ float g_tv[2048 * 128];
__device__ u64 g_ow1p[8 * 32 * 128];    // pre-packed ow1 col-pairs per 32-k chunk
__device__ u64 g_ow2p[8 * 32 * 96];     // pre-packed ow2
__device__ unsigned g_cnt;
__device__ unsigned g_gen;

// ---------------- helpers ----------------
__device__ __forceinline__ u64 pkxy(float x, float y) {
    u64 r; asm("mov.b64 %0, {%1, %2};" : "=l"(r) : "f"(x), "f"(y)); return r;
}
__device__ __forceinline__ void fma2(u64& d, u64 a, u64 b) {
    asm("fma.rn.f32x2 %0, %1, %2, %0;" : "+l"(d) : "l"(a), "l"(b));
}
__device__ __forceinline__ float2 up2(u64 v) {
    float2 f; asm("mov.b64 {%0, %1}, %2;" : "=f"(f.x), "=f"(f.y) : "l"(v)); return f;
}
__device__ __forceinline__ void sts_dup(unsigned addr, float v) {
    asm volatile("st.shared.v2.b32 [%0], {%1, %1};" :: "r"(addr), "f"(v));
}
__device__ __forceinline__ float sigm(float x) { return 1.f / (1.f + expf(-x)); }

// epoch grid barrier: monotonic counter, release/acquire
__device__ __forceinline__ void gbar_ep(unsigned target) {
    __syncthreads();
    if (threadIdx.x == 0) {
        unsigned old;
        asm volatile("atom.release.gpu.global.add.u32 %0, [%1], %2;"
                     : "=r"(old) : "l"(&g_cnt), "r"(1u) : "memory");
        if (old + 1u == target) {
            asm volatile("st.release.gpu.global.u32 [%0], %1;"
                         :: "l"(&g_gen), "r"(target) : "memory");
        } else {
            unsigned cur;
            do {
                asm volatile("ld.acquire.gpu.global.u32 %0, [%1];"
                             : "=r"(cur) : "l"(&g_gen) : "memory");
            } while (cur < target);
        }
    }
    __syncthreads();
}

// 8-row x 4-u64 inner micro step (shared by k_gemm and k_big stage1)
__device__ __forceinline__ void mk8x4(const u64* __restrict__ Adk,
                                      const u64* __restrict__ br, u64* acc) {
    ulonglong2 a01 = *(const ulonglong2*)(Adk);
    ulonglong2 a23 = *(const ulonglong2*)(Adk + 2);
    ulonglong2 a45 = *(const ulonglong2*)(Adk + 4);
    ulonglong2 a67 = *(const ulonglong2*)(Adk + 6);
    u64 b0 = br[0], b1 = br[32], b2 = br[64], b3 = br[96];
    fma2(acc[0], a01.x, b0); fma2(acc[1], a01.x, b1); fma2(acc[2], a01.x, b2); fma2(acc[3], a01.x, b3);
    fma2(acc[4], a01.y, b0); fma2(acc[5], a01.y, b1); fma2(acc[6], a01.y, b2); fma2(acc[7], a01.y, b3);
    fma2(acc[8], a23.x, b0); fma2(acc[9], a23.x, b1); fma2(acc[10], a23.x, b2); fma2(acc[11], a23.x, b3);
    fma2(acc[12], a23.y, b0); fma2(acc[13], a23.y, b1); fma2(acc[14], a23.y, b2); fma2(acc[15], a23.y, b3);
    fma2(acc[16], a45.x, b0); fma2(acc[17], a45.x, b1); fma2(acc[18], a45.x, b2); fma2(acc[19], a45.x, b3);
    fma2(acc[20], a45.y, b0); fma2(acc[21], a45.y, b1); fma2(acc[22], a45.y, b2); fma2(acc[23], a45.y, b3);
    fma2(acc[24], a67.x, b0); fma2(acc[25], a67.x, b1); fma2(acc[26], a67.x, b2); fma2(acc[27], a67.x, b3);
    fma2(acc[28], a67.y, b0); fma2(acc[29], a67.y, b1); fma2(acc[30], a67.y, b2); fma2(acc[31], a67.y, b3);
}

// ---------------- k_prep ----------------
__global__ __launch_bounds__(256) void k_prep(const float* __restrict__ mels,
                                              const float* __restrict__ w0,
                                              const float* __restrict__ ow1,
                                              const float* __restrict__ ow2) {
    int i0 = blockIdx.x * 256 + threadIdx.x;
    int stride = gridDim.x * 256;
    if (i0 == 0) { g_cnt = 0; g_gen = 0; }
    for (int e = i0; e < 2048 * 96; e += stride) {
        int r = e / 96, k = e - r * 96;
        int t = r >> 3, b = r & 7;
        g_arwin[e] = (k < 80 && t > 0) ? mels[((size_t)b * 80 + k) * 256 + t - 1] : 0.f;
    }
    for (int e = i0; e < 256 * 96; e += stride) {
        int c = e / 96, k = e - c * 96;
        g_w0p[e] = (k < 80) ? w0[c * 80 + k] : 0.f;
    }
    for (int e = i0; e < 32768; e += stride) {   // ow1 pack
        int ch = e >> 12, rem = e & 4095, kk = rem >> 7, p = rem & 127;
        int ca = (p & 31) + 64 * (p >> 5), cb = ca + 32;
        int k = ch * 32 + kk;
        g_ow1p[e] = pkxy(ow1[ca * 256 + k], ow1[cb * 256 + k]);
    }
    for (int e = i0; e < 24576; e += stride) {   // ow2 pack (clamped to col 160)
        int ch = e / 3072, rem = e - ch * 3072, kk = rem / 96, p = rem - kk * 96;
        int ca = (p & 31) + 64 * (p >> 5), cb = ca + 32;
        if (ca > 160) ca = 160;
        if (cb > 160) cb = 160;
        int k = ch * 32 + kk;
        g_ow2p[e] = pkxy(ow2[ca * 256 + k], ow2[cb * 256 + k]);
    }
}

// ---------------- generic GEMM: 128x256 tile, 512 thr ----------------
// dyn smem: Ad[32][128] u64 (32KB) + Bs[32][128] u64 (32KB) = 64KB
__global__ __launch_bounds__(512) void k_gemm(
    const float* __restrict__ A, int lda, int K,
    const float* __restrict__ W, int ldw, int wmax,
    const float* __restrict__ b1, const float* __restrict__ b2,
    float* __restrict__ C, int ldc, int relu) {
    u64* Ad = (u64*)dynsm;
    u64* Bs = (u64*)(dynsm + 32768);
    unsigned ad_base = (unsigned)__cvta_generic_to_shared(Ad);
    int tid = threadIdx.x, w = tid >> 5, lane = tid & 31;
    int r0 = blockIdx.x * 128, c0 = blockIdx.y * 256;
    u64 acc[32];
#pragma unroll
    for (int i = 0; i < 32; ++i) acc[i] = 0ull;
    int ar = tid & 127, kq = (tid >> 7) * 8;
    const float* Arow = A + (size_t)(r0 + ar) * lda + kq;
    int bp = tid & 127, kg = (tid >> 7) * 8;
    int ca = c0 + (bp & 31) + 64 * (bp >> 5);
    int cb = ca + 32;
    if (ca > wmax) ca = wmax;
    if (cb > wmax) cb = wmax;
    const float* wa = W + (size_t)ca * ldw + kg;
    const float* wb = W + (size_t)cb * ldw + kg;

    for (int k0 = 0; k0 < K; k0 += 32) {
        __syncthreads();
        {   // duplicated A: Ad[kk][128 rows]
            float4 v0 = *(const float4*)(Arow + k0);
            float4 v1 = *(const float4*)(Arow + k0 + 4);
            unsigned a0 = ad_base + (kq * 128 + ar) * 8;
            sts_dup(a0 + 0 * 1024, v0.x); sts_dup(a0 + 1 * 1024, v0.y);
            sts_dup(a0 + 2 * 1024, v0.z); sts_dup(a0 + 3 * 1024, v0.w);
            sts_dup(a0 + 4 * 1024, v1.x); sts_dup(a0 + 5 * 1024, v1.y);
            sts_dup(a0 + 6 * 1024, v1.z); sts_dup(a0 + 7 * 1024, v1.w);
        }
        {   // packed B col-pairs
            float4 va0 = *(const float4*)(wa + k0);
            float4 va1 = *(const float4*)(wa + k0 + 4);
            float4 vb0 = *(const float4*)(wb + k0);
            float4 vb1 = *(const float4*)(wb + k0 + 4);
            u64* dst = Bs + kg * 128 + bp;
            dst[0 * 128] = pkxy(va0.x, vb0.x); dst[1 * 128] = pkxy(va0.y, vb0.y);
            dst[2 * 128] = pkxy(va0.z, vb0.z); dst[3 * 128] = pkxy(va0.w, vb0.w);
            dst[4 * 128] = pkxy(va1.x, vb1.x); dst[5 * 128] = pkxy(va1.y, vb1.y);
            dst[6 * 128] = pkxy(va1.z, vb1.z); dst[7 * 128] = pkxy(va1.w, vb1.w);
        }
        __syncthreads();
#pragma unroll 4
        for (int kk = 0; kk < 32; ++kk)
            mk8x4(&Ad[kk * 128 + w * 8], Bs + kk * 128 + lane, acc);
    }
    float bxa[4], bxb[4];
#pragma unroll
    for (int j = 0; j < 4; ++j) {
        int c = c0 + lane + 64 * j;
        bxa[j] = (b1 ? b1[c] : 0.f) + (b2 ? b2[c] : 0.f);
        bxb[j] = (b1 ? b1[c + 32] : 0.f) + (b2 ? b2[c + 32] : 0.f);
    }
#pragma unroll
    for (int i = 0; i < 8; ++i) {
        float* cr = C + (size_t)(r0 + w * 8 + i) * ldc + c0;
#pragma unroll
        for (int j = 0; j < 4; ++j) {
            float2 v = up2(acc[i * 4 + j]);
            float x = v.x + bxa[j], y = v.y + bxb[j];
            if (relu) { x = fmaxf(x, 0.f); y = fmaxf(y, 0.f); }
            cr[lane + 64 * j] = x;
            cr[lane + 64 * j + 32] = y;
        }
    }
}

// ---------------- k_scan: LSTM recurrence (unchanged, passing) ----------------
#define SCAN_SMEM ((32 + 8) * 516 * 4)
__global__ __launch_bounds__(256) void k_scan(const float* __restrict__ whh) {
    float* wsm = (float*)dynsm;
    float* hs = (float*)dynsm + 32 * 516;
    int tid = threadIdx.x, cta = blockIdx.x;
    int mbase = cta * 8;
    {
        int rowid = tid >> 3, seg = tid & 7;
        int g = rowid & 3, ml = rowid >> 2;
        const float* src = whh + (size_t)(g * 512 + mbase + ml) * 512 + seg * 64;
        float* dst = wsm + rowid * 516 + seg * 64;
#pragma unroll
        for (int q = 0; q < 64; q += 4) *(float4*)(dst + q) = *(const float4*)(src + q);
    }
    int gt = cta * 256 + tid;
    if (gt < 8192) g_hbuf[gt] = 0.f;

    int b = tid & 7, gate = (tid >> 3) & 3, ml = tid >> 5;
    int m = mbase + ml;
    float cst = 0.f;
    unsigned epoch = 1;
    gbar_ep(epoch * 64);

    int cur = 0;
    for (int t = 0; t < T_STEPS; ++t) {
        float gihv0 = 0.f, gihv1 = 0.f, gihv2 = 0.f, gihv3 = 0.f;
        if (gate == 0) {
            const float* gp = g_gih + ((size_t)t * 8 + b) * 2048 + m;
            gihv0 = __ldg(gp); gihv1 = __ldg(gp + 512);
            gihv2 = __ldg(gp + 1024); gihv3 = __ldg(gp + 1536);
        }
        {
            int bb = tid >> 5, k0 = (tid & 31) * 16;
            const float4* src = (const float4*)(g_hbuf + cur * 4096 + bb * 512 + k0);
            float* dst = hs + bb * 516 + k0;
#pragma unroll
            for (int q = 0; q < 4; ++q) *(float4*)(dst + q * 4) = __ldcg(src + q);
        }
        __syncthreads();
        u64 acc = 0ull;
        const float* wr = wsm + (ml * 4 + gate) * 516;
        const float* hr = hs + b * 516;
#pragma unroll 8
        for (int k = 0; k < 512; k += 8) {
            ulonglong2 wa = *(const ulonglong2*)(wr + k);
            ulonglong2 wb = *(const ulonglong2*)(wr + k + 4);
            ulonglong2 ha = *(const ulonglong2*)(hr + k);
            ulonglong2 hb = *(const ulonglong2*)(hr + k + 4);
            fma2(acc, wa.x, ha.x); fma2(acc, wa.y, ha.y);
            fma2(acc, wb.x, hb.x); fma2(acc, wb.y, hb.y);
        }
        float2 dv = up2(acc);
        float dot = dv.x + dv.y;
        int lb = tid & 7;
        float d0 = __shfl_sync(0xffffffffu, dot, lb + 0);
        float d1 = __shfl_sync(0xffffffffu, dot, lb + 8);
        float d2 = __shfl_sync(0xffffffffu, dot, lb + 16);
        float d3 = __shfl_sync(0xffffffffu, dot, lb + 24);
        if (gate == 0) {
            float gi = gihv0 + d0, gf = gihv1 + d1, gg = gihv2 + d2, go = gihv3 + d3;
            float cn = sigm(gf) * cst + sigm(gi) * tanhf(gg);
            float hn = sigm(go) * tanhf(cn);
            cst = cn;
            __stcg(&g_hbuf[(cur ^ 1) * 4096 + b * 512 + m], hn);
            g_hall[((size_t)t * 8 + b) * 512 + m] = hn;
        }
        cur ^= 1;
        epoch++;
        gbar_ep(epoch * 64);
    }
}

// ---------------- k_big: fused obs-net + emission, one CTA per (t, batch) ----------------
// 512 thr. smem: a2s[128][260] f32 (133120) + Ad[32][128] u64 (32768) + Bs[32][128] u64 (32768)
#define BIG_SMEM (133120 + 32768 + 32768)
__global__ __launch_bounds__(512) void k_big(
    const float* __restrict__ mels, const float* __restrict__ ob1,
    const float* __restrict__ ob2, const int* __restrict__ inputs_len) {
    float* a2s = (float*)dynsm;                  // [128][260]
    u64* Ad = (u64*)(dynsm + 133120);            // [32][128]
    u64* Bs = (u64*)(dynsm + 133120 + 32768);    // [32][128] (stage2 [32][96])
    __shared__ float xs[80];
    __shared__ int ilen_s;
    unsigned ad_base = (unsigned)__cvta_generic_to_shared(Ad);
    int tid = threadIdx.x, w = tid >> 5, lane = tid & 31;
    int bid = blockIdx.x;
    int b = bid & 7, t = bid >> 3;
    int r0 = b * 128;

    if (tid < 80) xs[tid] = mels[((size_t)b * 80 + tid) * 256 + t];
    if (tid == 80) ilen_s = inputs_len[b];

    int ar = tid & 127, kq = (tid >> 7) * 8;
    const float* bp_ = g_base + (size_t)(r0 + ar) * 256 + kq;
    const float* hp_ = g_hpart + ((size_t)t * 8 + b) * 256 + kq;

    // ---- stage 1: a2 = relu(a1 @ ow1^T + ob1), 256 cols ----
    u64 acc[32];
#pragma unroll
    for (int i = 0; i < 32; ++i) acc[i] = 0ull;
    for (int ch = 0; ch < 8; ++ch) {
        int k0 = ch * 32;
        __syncthreads();
        {   // duplicated a1 = relu(base + hpart)
            float4 bv0 = *(const float4*)(bp_ + k0);
            float4 bv1 = *(const float4*)(bp_ + k0 + 4);
            float4 hv0 = *(const float4*)(hp_ + k0);
            float4 hv1 = *(const float4*)(hp_ + k0 + 4);
            unsigned a0 = ad_base + (kq * 128 + ar) * 8;
            sts_dup(a0 + 0 * 1024, fmaxf(bv0.x + hv0.x, 0.f));
            sts_dup(a0 + 1 * 1024, fmaxf(bv0.y + hv0.y, 0.f));
            sts_dup(a0 + 2 * 1024, fmaxf(bv0.z + hv0.z, 0.f));
            sts_dup(a0 + 3 * 1024, fmaxf(bv0.w + hv0.w, 0.f));
            sts_dup(a0 + 4 * 1024, fmaxf(bv1.x + hv1.x, 0.f));
            sts_dup(a0 + 5 * 1024, fmaxf(bv1.y + hv1.y, 0.f));
            sts_dup(a0 + 6 * 1024, fmaxf(bv1.z + hv1.z, 0.f));
            sts_dup(a0 + 7 * 1024, fmaxf(bv1.w + hv1.w, 0.f));
        }
        {   // copy pre-packed ow1 chunk (4096 u64 / 512 thr)
            const u64* src = g_ow1p + ch * 4096 + tid * 8;
            u64* dst = Bs + tid * 8;
            ulonglong2 v0 = *(const ulonglong2*)(src);
            ulonglong2 v1 = *(const ulonglong2*)(src + 2);
            ulonglong2 v2 = *(const ulonglong2*)(src + 4);
            ulonglong2 v3 = *(const ulonglong2*)(src + 6);
            *(ulonglong2*)(dst) = v0; *(ulonglong2*)(dst + 2) = v1;
            *(ulonglong2*)(dst + 4) = v2; *(ulonglong2*)(dst + 6) = v3;
        }
        __syncthreads();
#pragma unroll 4
        for (int kk = 0; kk < 32; ++kk)
            mk8x4(&Ad[kk * 128 + w * 8], Bs + kk * 128 + lane, acc);
    }
    __syncthreads();
    {   // write a2 row-major [128][260]
        float o1a[4], o1b[4];
#pragma unroll
        for (int j = 0; j < 4; ++j) {
            o1a[j] = ob1[lane + 64 * j];
            o1b[j] = ob1[lane + 64 * j + 32];
        }
#pragma unroll
        for (int i = 0; i < 8; ++i) {
            float* row = a2s + (w * 8 + i) * 260;
#pragma unroll
            for (int j = 0; j < 4; ++j) {
                float2 v = up2(acc[i * 4 + j]);
                row[lane + 64 * j] = fmaxf(v.x + o1a[j], 0.f);
                row[lane + 64 * j + 32] = fmaxf(v.y + o1b[j], 0.f);
            }
        }
    }
    // ---- stage 2: p = a2 @ ow2^T + ob2 (161 cols via 192) ----
    u64 acc2[24];
#pragma unroll
    for (int i = 0; i < 24; ++i) acc2[i] = 0ull;
    for (int ch = 0; ch < 8; ++ch) {
        int k0 = ch * 32;
        __syncthreads();
        {   // duplicated a2
            float4 av0 = *(const float4*)&a2s[ar * 260 + k0 + kq];
            float4 av1 = *(const float4*)&a2s[ar * 260 + k0 + kq + 4];
            unsigned a0 = ad_base + (kq * 128 + ar) * 8;
            sts_dup(a0 + 0 * 1024, av0.x); sts_dup(a0 + 1 * 1024, av0.y);
            sts_dup(a0 + 2 * 1024, av0.z); sts_dup(a0 + 3 * 1024, av0.w);
            sts_dup(a0 + 4 * 1024, av1.x); sts_dup(a0 + 5 * 1024, av1.y);
            sts_dup(a0 + 6 * 1024, av1.z); sts_dup(a0 + 7 * 1024, av1.w);
        }
        {   // copy pre-packed ow2 chunk (3072 u64 / 512 thr)
            const u64* src = g_ow2p + ch * 3072 + tid * 6;
            u64* dst = Bs + tid * 6;
            ulonglong2 v0 = *(const ulonglong2*)(src);
            ulonglong2 v1 = *(const ulonglong2*)(src + 2);
            ulonglong2 v2 = *(const ulonglong2*)(src + 4);
            *(ulonglong2*)(dst) = v0; *(ulonglong2*)(dst + 2) = v1;
            *(ulonglong2*)(dst + 4) = v2;
        }
        __syncthreads();
#pragma unroll 4
        for (int kk = 0; kk < 32; ++kk) {
            const u64* arp = &Ad[kk * 128 + w * 8];
            ulonglong2 a01 = *(const ulonglong2*)(arp);
            ulonglong2 a23 = *(const ulonglong2*)(arp + 2);
            ulonglong2 a45 = *(const ulonglong2*)(arp + 4);
            ulonglong2 a67 = *(const ulonglong2*)(arp + 6);
            const u64* br = Bs + kk * 96 + lane;
            u64 b0 = br[0], b1 = br[32], b2 = br[64];
            fma2(acc2[0], a01.x, b0); fma2(acc2[1], a01.x, b1); fma2(acc2[2], a01.x, b2);
            fma2(acc2[3], a01.y, b0); fma2(acc2[4], a01.y, b1); fma2(acc2[5], a01.y, b2);
            fma2(acc2[6], a23.x, b0); fma2(acc2[7], a23.x, b1); fma2(acc2[8], a23.x, b2);
            fma2(acc2[9], a23.y, b0); fma2(acc2[10], a23.y, b1); fma2(acc2[11], a23.y, b2);
            fma2(acc2[12], a45.x, b0); fma2(acc2[13], a45.x, b1); fma2(acc2[14], a45.x, b2);
            fma2(acc2[15], a45.y, b0); fma2(acc2[16], a45.y, b1); fma2(acc2[17], a45.y, b2);
            fma2(acc2[18], a67.x, b0); fma2(acc2[19], a67.x, b1); fma2(acc2[20], a67.x, b2);
            fma2(acc2[21], a67.y, b0); fma2(acc2[22], a67.y, b1); fma2(acc2[23], a67.y, b2);
        }
    }
    __syncthreads();
    float* ps = a2s;   // overlay [128][164]
#pragma unroll
    for (int i = 0; i < 8; ++i) {
        int row = w * 8 + i;
#pragma unroll
        for (int j = 0; j < 3; ++j) {
            float2 v = up2(acc2[i * 3 + j]);
            int c = lane + 64 * j;
            if (c < 161) ps[row * 164 + c] = v.x + ob2[c];
            int c2 = c + 32;
            if (c2 < 161) ps[row * 164 + c2] = v.y + ob2[c2];
        }
    }
    __syncthreads();
    {   // emission: warp w -> rows w*8..+8; 4 lanes per row, 20 d's each
        int ri = lane >> 2, part = lane & 3;
        int row = w * 8 + ri;
        const float* pr = ps + row * 164;
        float sum = 0.f;
        int d0 = part * 20;
        for (int d = d0; d < d0 + 20; ++d) {
            float mean = pr[d], sh = pr[80 + d];
            float stdv = fmaxf(sh, 0.f) + log1pf(expf(-fabsf(sh))) + 1e-3f;
            float z = (xs[d] - mean) / stdv;
            sum += -0.5f * z * z - logf(stdv) - HALF_LOG2PI;
        }
        sum += __shfl_xor_sync(0xffffffffu, sum, 1);
        sum += __shfl_xor_sync(0xffffffffu, sum, 2);
        if (part == 0) {
            int n = row;
            g_em[((size_t)t * 8 + b) * 128 + n] = (n < ilen_s) ? sum : 0.f;
            g_tv[((size_t)t * 8 + b) * 128 + n] = pr[160];
        }
    }
}

// ---------------- k_hmm: one warp per batch, shuffle-only ----------------
__global__ __launch_bounds__(32) void k_hmm(
    const int* __restrict__ inputs_len, const int* __restrict__ mel_lens,
    float* __restrict__ out) {
    int b = blockIdx.x, lane = threadIdx.x;
    int ilen = inputs_len[b], mlen = mel_lens[b];
    float la[4];
    float lp = 0.f;
    float* outla = out + 8 + (size_t)b * 256 * 128;
    float emc[4], tvc[4];
#pragma unroll
    for (int q = 0; q < 4; ++q) {
        emc[q] = g_em[(size_t)b * 128 + q * 32 + lane];
        tvc[q] = g_tv[(size_t)b * 128 + q * 32 + lane];
    }
    for (int t = 0; t < T_STEPS; ++t) {
        float emn[4], tvn[4];
        if (t + 1 < T_STEPS) {
#pragma unroll
            for (int q = 0; q < 4; ++q) {
                emn[q] = __ldcg(&g_em[((size_t)(t + 1) * 8 + b) * 128 + q * 32 + lane]);
                tvn[q] = __ldcg(&g_tv[((size_t)(t + 1) * 8 + b) * 128 + q * 32 + lane]);
            }
        }
        float la_t[4];
        if (t == 0) {
#pragma unroll
            for (int q = 0; q < 4; ++q)
                la_t[q] = emc[q] + ((q == 0 && lane == 0) ? 0.f : NEG);
        } else {
            float st_[4], mvv[4];
#pragma unroll
            for (int q = 0; q < 4; ++q) {
                float tv = tvc[q];
                float lstay = logf(fmaxf(1.f / (1.f + expf(tv)), 1e-4f));
                float lmove = logf(fmaxf(1.f / (1.f + expf(-tv)), 1e-4f));
                st_[q] = la[q] + lstay;
                mvv[q] = la[q] + lmove;
            }
            float lv[4];
#pragma unroll
            for (int q = 0; q < 4; ++q)
                lv[q] = __shfl_up_sync(0xffffffffu, mvv[q], 1);
            float c1 = __shfl_sync(0xffffffffu, mvv[0], 31);
            float c2 = __shfl_sync(0xffffffffu, mvv[1], 31);
            float c3 = __shfl_sync(0xffffffffu, mvv[2], 31);
            if (lane == 0) { lv[0] = NEG; lv[1] = c1; lv[2] = c2; lv[3] = c3; }
#pragma unroll
            for (int q = 0; q < 4; ++q) {
                float mx = fmaxf(st_[q], lv[q]);
                float mn = fminf(st_[q], lv[q]);
                float o = mx + log1pf(expf(mn - mx));
                int n = q * 32 + lane;
                o = (n < ilen) ? o : NEG;
                la_t[q] = emc[q] + o;
            }
        }
        float mx = fmaxf(fmaxf(la_t[0], la_t[1]), fmaxf(la_t[2], la_t[3]));
#pragma unroll
        for (int off = 16; off; off >>= 1)
            mx = fmaxf(mx, __shfl_xor_sync(0xffffffffu, mx, off));
        float s = expf(la_t[0] - mx) + expf(la_t[1] - mx) +
                  expf(la_t[2] - mx) + expf(la_t[3] - mx);
#pragma unroll
        for (int off = 16; off; off >>= 1)
            s += __shfl_xor_sync(0xffffffffu, s, off);
        float log_c = mx + logf(s);
#pragma unroll
        for (int q = 0; q < 4; ++q) {
            la[q] = la_t[q] - log_c;
            outla[(size_t)t * 128 + q * 32 + lane] = la[q];
        }
        if (t < mlen) lp += log_c;
#pragma unroll
        for (int q = 0; q < 4; ++q) { emc[q] = emn[q]; tvc[q] = tvn[q]; }
    }
    if (lane == 0) out[b] = lp;
}

// ---------------- launch ----------------
extern "C" void kernel_launch(void* const* d_in, const int* in_sizes, int n_in,
                              void* d_out, int out_size) {
    const float* inputs = (const float*)d_in[0];
    const float* mels = (const float*)d_in[1];
    const float* pw0 = (const float*)d_in[2];
    const float* pw1 = (const float*)d_in[3];
    const float* wih = (const float*)d_in[4];
    const float* whh = (const float*)d_in[5];
    const float* bih = (const float*)d_in[6];
    const float* bhh = (const float*)d_in[7];
    const float* ow0 = (const float*)d_in[8];
    const float* ob0 = (const float*)d_in[9];
    const float* ow1 = (const float*)d_in[10];
    const float* ob1 = (const float*)d_in[11];
    const float* ow2 = (const float*)d_in[12];
    const float* ob2 = (const float*)d_in[13];
    const int* inputs_len = (const int*)d_in[14];
    const int* mel_lens = (const int*)d_in[15];
    float* out = (float*)d_out;

    cudaFuncSetAttribute(k_scan, cudaFuncAttributeMaxDynamicSharedMemorySize, SCAN_SMEM);
    cudaFuncSetAttribute(k_big, cudaFuncAttributeMaxDynamicSharedMemorySize, BIG_SMEM);
    cudaFuncSetAttribute(k_gemm, cudaFuncAttributeMaxDynamicSharedMemorySize, 65536);

    float *arwin, *w0p, *pre, *base, *hall, *hpart, *gih;
    cudaGetSymbolAddress((void**)&arwin, g_arwin);
    cudaGetSymbolAddress((void**)&w0p, g_w0p);
    cudaGetSymbolAddress((void**)&pre, g_pre);
    cudaGetSymbolAddress((void**)&base, g_base);
    cudaGetSymbolAddress((void**)&hall, g_hall);
    cudaGetSymbolAddress((void**)&hpart, g_hpart);
    cudaGetSymbolAddress((void**)&gih, g_gih);

    k_prep<<<256, 256>>>(mels, pw0, ow1, ow2);
    // p0 = relu(arwin @ w0p^T) -> g_hpart (scratch)
    k_gemm<<<dim3(16, 1), 512, 65536>>>(arwin, 96, 96, w0p, 96, 255, nullptr, nullptr, hpart, 256, 1);
    // pre1 = relu(p0 @ pw1^T) -> g_pre
    k_gemm<<<dim3(16, 1), 512, 65536>>>(hpart, 256, 256, pw1, 256, 255, nullptr, nullptr, pre, 256, 1);
    // gih = pre1 @ wih^T + bih + bhh
    k_gemm<<<dim3(16, 8), 512, 65536>>>(pre, 256, 256, wih, 256, 2047, bih, bhh, gih, 2048, 0);
    // base = inputs @ ow0[:, :512]^T + ob0
    k_gemm<<<dim3(8, 1), 512, 65536>>>(inputs, 512, 512, ow0, 1024, 255, ob0, nullptr, base, 256, 0);
    // LSTM scan
    k_scan<<<64, 256, SCAN_SMEM>>>(whh);
    // hpart = hall @ ow0[:, 512:]^T
    k_gemm<<<dim3(16, 1), 512, 65536>>>(hall, 512, 512, ow0 + 512, 1024, 255, nullptr, nullptr, hpart, 256, 0);
    // fused obs-net + emission: one CTA per (t, batch)
    k_big<<<2048, 512, BIG_SMEM>>>(mels, ob1, ob2, inputs_len);
    // HMM forward
    k_hmm<<<8, 32>>>(inputs_len, mel_lens, out);
}

// round 10
// speedup vs baseline: 1.1696x; 1.1044x over previous
#include <cuda_runtime.h>
#include <cstdint>

#define T_STEPS 256
#define NEG (-1.0e10f)
#define HALF_LOG2PI 0.9189385332046727f
typedef unsigned long long u64;

extern __shared__ char dynsm[];   // single dynamic-smem symbol

// ---------------- global scratch ----------------
__device__ float g_arwin[2048 * 96];
__device__ float g_w0p[256 * 96];
__device__ float g_pre[2048 * 256];
__device__ float g_gih[2048 * 2048];
__device__ float g_base[1024 * 256];
__device__ float g_hall[2048 * 512];
__device__ float g_hpart[2048 * 256];   // also p0 scratch
__device__ float g_hbuf[8192];
__device__ float g_em[2048 * 128];
__device__ float g_tv[2048 * 128];
__device__ u64 g_ow1p[8 * 32 * 128];    // pre-packed ow1 col-pairs per 32-k chunk
__device__ u64 g_ow2p[8 * 32 * 96];     // pre-packed ow2
__device__ unsigned g_cnt;
__device__ unsigned g_gen;

// ---------------- helpers ----------------
__device__ __forceinline__ u64 pk2(float x) {
    u64 r; asm("mov.b64 %0, {%1, %1};" : "=l"(r) : "f"(x)); return r;
}
__device__ __forceinline__ u64 pkxy(float x, float y) {
    u64 r; asm("mov.b64 %0, {%1, %2};" : "=l"(r) : "f"(x), "f"(y)); return r;
}
__device__ __forceinline__ void fma2(u64& d, u64 a, u64 b) {
    asm("fma.rn.f32x2 %0, %1, %2, %0;" : "+l"(d) : "l"(a), "l"(b));
}
__device__ __forceinline__ float2 up2(u64 v) {
    float2 f; asm("mov.b64 {%0, %1}, %2;" : "=f"(f.x), "=f"(f.y) : "l"(v)); return f;
}
__device__ __forceinline__ float sigm(float x) { return 1.f / (1.f + expf(-x)); }

// epoch grid barrier: monotonic counter, release/acquire
__device__ __forceinline__ void gbar_ep(unsigned target) {
    __syncthreads();
    if (threadIdx.x == 0) {
        unsigned old;
        asm volatile("atom.release.gpu.global.add.u32 %0, [%1], %2;"
                     : "=r"(old) : "l"(&g_cnt), "r"(1u) : "memory");
        if (old + 1u == target) {
            asm volatile("st.release.gpu.global.u32 [%0], %1;"
                         :: "l"(&g_gen), "r"(target) : "memory");
        } else {
            unsigned cur;
            do {
                asm volatile("ld.acquire.gpu.global.u32 %0, [%1];"
                             : "=r"(cur) : "l"(&g_gen) : "memory");
            } while (cur < target);
        }
    }
    __syncthreads();
}

#define AS_LD 132   // f32 stride for transposed A tile [32][AS_LD]
#define AS_BYTES (32 * AS_LD * 4)   // 16896

// inner micro step: 8 rows (f32, packed on the fly) x 4 u64-cols
__device__ __forceinline__ void mk_f32(const float* __restrict__ Ak,
                                       const u64* __restrict__ br, u64* acc) {
    float4 a0 = *(const float4*)(Ak);
    float4 a1 = *(const float4*)(Ak + 4);
    u64 b0 = br[0], b1 = br[32], b2 = br[64], b3 = br[96];
    u64 p;
    p = pk2(a0.x); fma2(acc[0], p, b0); fma2(acc[1], p, b1); fma2(acc[2], p, b2); fma2(acc[3], p, b3);
    p = pk2(a0.y); fma2(acc[4], p, b0); fma2(acc[5], p, b1); fma2(acc[6], p, b2); fma2(acc[7], p, b3);
    p = pk2(a0.z); fma2(acc[8], p, b0); fma2(acc[9], p, b1); fma2(acc[10], p, b2); fma2(acc[11], p, b3);
    p = pk2(a0.w); fma2(acc[12], p, b0); fma2(acc[13], p, b1); fma2(acc[14], p, b2); fma2(acc[15], p, b3);
    p = pk2(a1.x); fma2(acc[16], p, b0); fma2(acc[17], p, b1); fma2(acc[18], p, b2); fma2(acc[19], p, b3);
    p = pk2(a1.y); fma2(acc[20], p, b0); fma2(acc[21], p, b1); fma2(acc[22], p, b2); fma2(acc[23], p, b3);
    p = pk2(a1.z); fma2(acc[24], p, b0); fma2(acc[25], p, b1); fma2(acc[26], p, b2); fma2(acc[27], p, b3);
    p = pk2(a1.w); fma2(acc[28], p, b0); fma2(acc[29], p, b1); fma2(acc[30], p, b2); fma2(acc[31], p, b3);
}

// ---------------- k_prep ----------------
__global__ __launch_bounds__(256) void k_prep(const float* __restrict__ mels,
                                              const float* __restrict__ w0,
                                              const float* __restrict__ ow1,
                                              const float* __restrict__ ow2) {
    int i0 = blockIdx.x * 256 + threadIdx.x;
    int stride = gridDim.x * 256;
    if (i0 == 0) { g_cnt = 0; g_gen = 0; }
    for (int e = i0; e < 2048 * 96; e += stride) {
        int r = e / 96, k = e - r * 96;
        int t = r >> 3, b = r & 7;
        g_arwin[e] = (k < 80 && t > 0) ? mels[((size_t)b * 80 + k) * 256 + t - 1] : 0.f;
    }
    for (int e = i0; e < 256 * 96; e += stride) {
        int c = e / 96, k = e - c * 96;
        g_w0p[e] = (k < 80) ? w0[c * 80 + k] : 0.f;
    }
    for (int e = i0; e < 32768; e += stride) {   // ow1 pack
        int ch = e >> 12, rem = e & 4095, kk = rem >> 7, p = rem & 127;
        int ca = (p & 31) + 64 * (p >> 5), cb = ca + 32;
        int k = ch * 32 + kk;
        g_ow1p[e] = pkxy(ow1[ca * 256 + k], ow1[cb * 256 + k]);
    }
    for (int e = i0; e < 24576; e += stride) {   // ow2 pack (clamped to col 160)
        int ch = e / 3072, rem = e - ch * 3072, kk = rem / 96, p = rem - kk * 96;
        int ca = (p & 31) + 64 * (p >> 5), cb = ca + 32;
        if (ca > 160) ca = 160;
        if (cb > 160) cb = 160;
        int k = ch * 32 + kk;
        g_ow2p[e] = pkxy(ow2[ca * 256 + k], ow2[cb * 256 + k]);
    }
}

// ---------------- generic GEMM: 128x256 tile, 512 thr, prefetched ----------------
// dyn smem: As f32 [32][132] (16896B) + Bs u64 [32][128] (32768B)
__global__ __launch_bounds__(512) void k_gemm(
    const float* __restrict__ A, int lda, int K,
    const float* __restrict__ W, int ldw, int wmax,
    const float* __restrict__ b1, const float* __restrict__ b2,
    float* __restrict__ C, int ldc, int relu) {
    float* As = (float*)dynsm;
    u64* Bs = (u64*)(dynsm + AS_BYTES);
    int tid = threadIdx.x, w = tid >> 5, lane = tid & 31;
    int r0 = blockIdx.x * 128, c0 = blockIdx.y * 256;
    u64 acc[32];
#pragma unroll
    for (int i = 0; i < 32; ++i) acc[i] = 0ull;
    int ar = tid & 127, kq = (tid >> 7) * 8;
    const float* Arow = A + (size_t)(r0 + ar) * lda + kq;
    int bp = tid & 127;
    int ca = c0 + (bp & 31) + 64 * (bp >> 5);
    int cb = ca + 32;
    if (ca > wmax) ca = wmax;
    if (cb > wmax) cb = wmax;
    const float* wa = W + (size_t)ca * ldw + kq;
    const float* wb = W + (size_t)cb * ldw + kq;
    int nch = K >> 5;

    // prefetch chunk 0
    float4 pa0 = *(const float4*)(Arow);
    float4 pa1 = *(const float4*)(Arow + 4);
    float4 qa0 = *(const float4*)(wa);
    float4 qa1 = *(const float4*)(wa + 4);
    float4 qb0 = *(const float4*)(wb);
    float4 qb1 = *(const float4*)(wb + 4);

    for (int ch = 0; ch < nch; ++ch) {
        if (ch) __syncthreads();
        {   // store A (plain f32, transposed)
            float* ap = As + kq * AS_LD + ar;
            ap[0 * AS_LD] = pa0.x; ap[1 * AS_LD] = pa0.y;
            ap[2 * AS_LD] = pa0.z; ap[3 * AS_LD] = pa0.w;
            ap[4 * AS_LD] = pa1.x; ap[5 * AS_LD] = pa1.y;
            ap[6 * AS_LD] = pa1.z; ap[7 * AS_LD] = pa1.w;
        }
        {   // store packed B col-pairs
            u64* dst = Bs + kq * 128 + bp;
            dst[0 * 128] = pkxy(qa0.x, qb0.x); dst[1 * 128] = pkxy(qa0.y, qb0.y);
            dst[2 * 128] = pkxy(qa0.z, qb0.z); dst[3 * 128] = pkxy(qa0.w, qb0.w);
            dst[4 * 128] = pkxy(qa1.x, qb1.x); dst[5 * 128] = pkxy(qa1.y, qb1.y);
            dst[6 * 128] = pkxy(qa1.z, qb1.z); dst[7 * 128] = pkxy(qa1.w, qb1.w);
        }
        __syncthreads();
        if (ch + 1 < nch) {   // prefetch next chunk (hidden under compute)
            int k0 = (ch + 1) * 32;
            pa0 = *(const float4*)(Arow + k0);
            pa1 = *(const float4*)(Arow + k0 + 4);
            qa0 = *(const float4*)(wa + k0);
            qa1 = *(const float4*)(wa + k0 + 4);
            qb0 = *(const float4*)(wb + k0);
            qb1 = *(const float4*)(wb + k0 + 4);
        }
#pragma unroll 8
        for (int kk = 0; kk < 32; ++kk)
            mk_f32(As + kk * AS_LD + w * 8, Bs + kk * 128 + lane, acc);
    }
    float bxa[4], bxb[4];
#pragma unroll
    for (int j = 0; j < 4; ++j) {
        int c = c0 + lane + 64 * j;
        bxa[j] = (b1 ? b1[c] : 0.f) + (b2 ? b2[c] : 0.f);
        bxb[j] = (b1 ? b1[c + 32] : 0.f) + (b2 ? b2[c + 32] : 0.f);
    }
#pragma unroll
    for (int i = 0; i < 8; ++i) {
        float* cr = C + (size_t)(r0 + w * 8 + i) * ldc + c0;
#pragma unroll
        for (int j = 0; j < 4; ++j) {
            float2 v = up2(acc[i * 4 + j]);
            float x = v.x + bxa[j], y = v.y + bxb[j];
            if (relu) { x = fmaxf(x, 0.f); y = fmaxf(y, 0.f); }
            cr[lane + 64 * j] = x;
            cr[lane + 64 * j + 32] = y;
        }
    }
}

// ---------------- k_scan: LSTM recurrence (unchanged, verified) ----------------
#define SCAN_SMEM ((32 + 8) * 516 * 4)
__global__ __launch_bounds__(256) void k_scan(const float* __restrict__ whh) {
    float* wsm = (float*)dynsm;
    float* hs = (float*)dynsm + 32 * 516;
    int tid = threadIdx.x, cta = blockIdx.x;
    int mbase = cta * 8;
    {
        int rowid = tid >> 3, seg = tid & 7;
        int g = rowid & 3, ml = rowid >> 2;
        const float* src = whh + (size_t)(g * 512 + mbase + ml) * 512 + seg * 64;
        float* dst = wsm + rowid * 516 + seg * 64;
#pragma unroll
        for (int q = 0; q < 64; q += 4) *(float4*)(dst + q) = *(const float4*)(src + q);
    }
    int gt = cta * 256 + tid;
    if (gt < 8192) g_hbuf[gt] = 0.f;

    int b = tid & 7, gate = (tid >> 3) & 3, ml = tid >> 5;
    int m = mbase + ml;
    float cst = 0.f;
    unsigned epoch = 1;
    gbar_ep(epoch * 64);

    int cur = 0;
    for (int t = 0; t < T_STEPS; ++t) {
        float gihv0 = 0.f, gihv1 = 0.f, gihv2 = 0.f, gihv3 = 0.f;
        if (gate == 0) {
            const float* gp = g_gih + ((size_t)t * 8 + b) * 2048 + m;
            gihv0 = __ldg(gp); gihv1 = __ldg(gp + 512);
            gihv2 = __ldg(gp + 1024); gihv3 = __ldg(gp + 1536);
        }
        {
            int bb = tid >> 5, k0 = (tid & 31) * 16;
            const float4* src = (const float4*)(g_hbuf + cur * 4096 + bb * 512 + k0);
            float* dst = hs + bb * 516 + k0;
#pragma unroll
            for (int q = 0; q < 4; ++q) *(float4*)(dst + q * 4) = __ldcg(src + q);
        }
        __syncthreads();
        u64 acc = 0ull;
        const float* wr = wsm + (ml * 4 + gate) * 516;
        const float* hr = hs + b * 516;
#pragma unroll 8
        for (int k = 0; k < 512; k += 8) {
            ulonglong2 wa = *(const ulonglong2*)(wr + k);
            ulonglong2 wb = *(const ulonglong2*)(wr + k + 4);
            ulonglong2 ha = *(const ulonglong2*)(hr + k);
            ulonglong2 hb = *(const ulonglong2*)(hr + k + 4);
            fma2(acc, wa.x, ha.x); fma2(acc, wa.y, ha.y);
            fma2(acc, wb.x, hb.x); fma2(acc, wb.y, hb.y);
        }
        float2 dv = up2(acc);
        float dot = dv.x + dv.y;
        int lb = tid & 7;
        float d0 = __shfl_sync(0xffffffffu, dot, lb + 0);
        float d1 = __shfl_sync(0xffffffffu, dot, lb + 8);
        float d2 = __shfl_sync(0xffffffffu, dot, lb + 16);
        float d3 = __shfl_sync(0xffffffffu, dot, lb + 24);
        if (gate == 0) {
            float gi = gihv0 + d0, gf = gihv1 + d1, gg = gihv2 + d2, go = gihv3 + d3;
            float cn = sigm(gf) * cst + sigm(gi) * tanhf(gg);
            float hn = sigm(go) * tanhf(cn);
            cst = cn;
            __stcg(&g_hbuf[(cur ^ 1) * 4096 + b * 512 + m], hn);
            g_hall[((size_t)t * 8 + b) * 512 + m] = hn;
        }
        cur ^= 1;
        epoch++;
        gbar_ep(epoch * 64);
    }
}

// ---------------- k_big: fused obs-net + emission, one CTA per (t, batch) ----------------
// 512 thr. smem: a2s[128][260] f32 (133120) + As[32][132] f32 (16896) + Bs[32][128] u64 (32768)
#define BIG_SMEM (133120 + AS_BYTES + 32768)
__global__ __launch_bounds__(512) void k_big(
    const float* __restrict__ mels, const float* __restrict__ ob1,
    const float* __restrict__ ob2, const int* __restrict__ inputs_len) {
    float* a2s = (float*)dynsm;                       // [128][260]
    float* As = (float*)(dynsm + 133120);             // [32][132]
    u64* Bs = (u64*)(dynsm + 133120 + AS_BYTES);      // [32][128] (stage2 [32][96])
    __shared__ float xs[80];
    __shared__ int ilen_s;
    int tid = threadIdx.x, w = tid >> 5, lane = tid & 31;
    int bid = blockIdx.x;
    int b = bid & 7, t = bid >> 3;
    int r0 = b * 128;

    if (tid < 80) xs[tid] = mels[((size_t)b * 80 + tid) * 256 + t];
    if (tid == 80) ilen_s = inputs_len[b];

    int ar = tid & 127, kq = (tid >> 7) * 8;
    const float* bp_ = g_base + (size_t)(r0 + ar) * 256 + kq;
    const float* hp_ = g_hpart + ((size_t)t * 8 + b) * 256 + kq;

    // ---- stage 1: a2 = relu(a1 @ ow1^T + ob1), 256 cols ----
    u64 acc[32];
#pragma unroll
    for (int i = 0; i < 32; ++i) acc[i] = 0ull;
    // prefetch chunk 0
    float4 pb0 = *(const float4*)(bp_);
    float4 pb1 = *(const float4*)(bp_ + 4);
    float4 ph0 = *(const float4*)(hp_);
    float4 ph1 = *(const float4*)(hp_ + 4);
    ulonglong2 q0 = *(const ulonglong2*)(g_ow1p + tid * 8);
    ulonglong2 q1 = *(const ulonglong2*)(g_ow1p + tid * 8 + 2);
    ulonglong2 q2 = *(const ulonglong2*)(g_ow1p + tid * 8 + 4);
    ulonglong2 q3 = *(const ulonglong2*)(g_ow1p + tid * 8 + 6);

    for (int ch = 0; ch < 8; ++ch) {
        if (ch) __syncthreads();
        {   // store a1 = relu(base + hpart), f32 transposed
            float* ap = As + kq * AS_LD + ar;
            ap[0 * AS_LD] = fmaxf(pb0.x + ph0.x, 0.f);
            ap[1 * AS_LD] = fmaxf(pb0.y + ph0.y, 0.f);
            ap[2 * AS_LD] = fmaxf(pb0.z + ph0.z, 0.f);
            ap[3 * AS_LD] = fmaxf(pb0.w + ph0.w, 0.f);
            ap[4 * AS_LD] = fmaxf(pb1.x + ph1.x, 0.f);
            ap[5 * AS_LD] = fmaxf(pb1.y + ph1.y, 0.f);
            ap[6 * AS_LD] = fmaxf(pb1.z + ph1.z, 0.f);
            ap[7 * AS_LD] = fmaxf(pb1.w + ph1.w, 0.f);
        }
        {   // store pre-packed B chunk
            u64* dst = Bs + tid * 8;
            *(ulonglong2*)(dst) = q0; *(ulonglong2*)(dst + 2) = q1;
            *(ulonglong2*)(dst + 4) = q2; *(ulonglong2*)(dst + 6) = q3;
        }
        __syncthreads();
        if (ch + 1 < 8) {   // prefetch next chunk
            int k0 = (ch + 1) * 32;
            pb0 = *(const float4*)(bp_ + k0);
            pb1 = *(const float4*)(bp_ + k0 + 4);
            ph0 = *(const float4*)(hp_ + k0);
            ph1 = *(const float4*)(hp_ + k0 + 4);
            const u64* src = g_ow1p + (ch + 1) * 4096 + tid * 8;
            q0 = *(const ulonglong2*)(src);
            q1 = *(const ulonglong2*)(src + 2);
            q2 = *(const ulonglong2*)(src + 4);
            q3 = *(const ulonglong2*)(src + 6);
        }
#pragma unroll 8
        for (int kk = 0; kk < 32; ++kk)
            mk_f32(As + kk * AS_LD + w * 8, Bs + kk * 128 + lane, acc);
    }
    __syncthreads();
    {   // write a2 row-major [128][260]
        float o1a[4], o1b[4];
#pragma unroll
        for (int j = 0; j < 4; ++j) {
            o1a[j] = ob1[lane + 64 * j];
            o1b[j] = ob1[lane + 64 * j + 32];
        }
#pragma unroll
        for (int i = 0; i < 8; ++i) {
            float* row = a2s + (w * 8 + i) * 260;
#pragma unroll
            for (int j = 0; j < 4; ++j) {
                float2 v = up2(acc[i * 4 + j]);
                row[lane + 64 * j] = fmaxf(v.x + o1a[j], 0.f);
                row[lane + 64 * j + 32] = fmaxf(v.y + o1b[j], 0.f);
            }
        }
    }
    __syncthreads();
    // ---- stage 2: p = a2 @ ow2^T + ob2 (161 cols via 192) ----
    u64 acc2[24];
#pragma unroll
    for (int i = 0; i < 24; ++i) acc2[i] = 0ull;
    ulonglong2 r0v = *(const ulonglong2*)(g_ow2p + tid * 6);
    ulonglong2 r1v = *(const ulonglong2*)(g_ow2p + tid * 6 + 2);
    ulonglong2 r2v = *(const ulonglong2*)(g_ow2p + tid * 6 + 4);
    for (int ch = 0; ch < 8; ++ch) {
        int k0 = ch * 32;
        if (ch) __syncthreads();
        {   // transpose a2 chunk into As (smem->smem)
            float4 av0 = *(const float4*)&a2s[ar * 260 + k0 + kq];
            float4 av1 = *(const float4*)&a2s[ar * 260 + k0 + kq + 4];
            float* ap = As + kq * AS_LD + ar;
            ap[0 * AS_LD] = av0.x; ap[1 * AS_LD] = av0.y;
            ap[2 * AS_LD] = av0.z; ap[3 * AS_LD] = av0.w;
            ap[4 * AS_LD] = av1.x; ap[5 * AS_LD] = av1.y;
            ap[6 * AS_LD] = av1.z; ap[7 * AS_LD] = av1.w;
        }
        {
            u64* dst = Bs + tid * 6;
            *(ulonglong2*)(dst) = r0v; *(ulonglong2*)(dst + 2) = r1v;
            *(ulonglong2*)(dst + 4) = r2v;
        }
        __syncthreads();
        if (ch + 1 < 8) {
            const u64* src = g_ow2p + (ch + 1) * 3072 + tid * 6;
            r0v = *(const ulonglong2*)(src);
            r1v = *(const ulonglong2*)(src + 2);
            r2v = *(const ulonglong2*)(src + 4);
        }
#pragma unroll 8
        for (int kk = 0; kk < 32; ++kk) {
            float4 a0 = *(const float4*)(As + kk * AS_LD + w * 8);
            float4 a1 = *(const float4*)(As + kk * AS_LD + w * 8 + 4);
            const u64* br = Bs + kk * 96 + lane;
            u64 b0 = br[0], b1 = br[32], b2 = br[64];
            u64 p;
            p = pk2(a0.x); fma2(acc2[0], p, b0); fma2(acc2[1], p, b1); fma2(acc2[2], p, b2);
            p = pk2(a0.y); fma2(acc2[3], p, b0); fma2(acc2[4], p, b1); fma2(acc2[5], p, b2);
            p = pk2(a0.z); fma2(acc2[6], p, b0); fma2(acc2[7], p, b1); fma2(acc2[8], p, b2);
            p = pk2(a0.w); fma2(acc2[9], p, b0); fma2(acc2[10], p, b1); fma2(acc2[11], p, b2);
            p = pk2(a1.x); fma2(acc2[12], p, b0); fma2(acc2[13], p, b1); fma2(acc2[14], p, b2);
            p = pk2(a1.y); fma2(acc2[15], p, b0); fma2(acc2[16], p, b1); fma2(acc2[17], p, b2);
            p = pk2(a1.z); fma2(acc2[18], p, b0); fma2(acc2[19], p, b1); fma2(acc2[20], p, b2);
            p = pk2(a1.w); fma2(acc2[21], p, b0); fma2(acc2[22], p, b1); fma2(acc2[23], p, b2);
        }
    }
    __syncthreads();
    float* ps = a2s;   // overlay [128][164]
#pragma unroll
    for (int i = 0; i < 8; ++i) {
        int row = w * 8 + i;
#pragma unroll
        for (int j = 0; j < 3; ++j) {
            float2 v = up2(acc2[i * 3 + j]);
            int c = lane + 64 * j;
            if (c < 161) ps[row * 164 + c] = v.x + ob2[c];
            int c2 = c + 32;
            if (c2 < 161) ps[row * 164 + c2] = v.y + ob2[c2];
        }
    }
    __syncthreads();
    {   // emission: warp w -> rows w*8..+8; 4 lanes per row, 20 d's each
        int ri = lane >> 2, part = lane & 3;
        int row = w * 8 + ri;
        const float* pr = ps + row * 164;
        float sum = 0.f;
        int d0 = part * 20;
        for (int d = d0; d < d0 + 20; ++d) {
            float mean = pr[d], sh = pr[80 + d];
            float stdv = fmaxf(sh, 0.f) + log1pf(expf(-fabsf(sh))) + 1e-3f;
            float z = (xs[d] - mean) / stdv;
            sum += -0.5f * z * z - logf(stdv) - HALF_LOG2PI;
        }
        sum += __shfl_xor_sync(0xffffffffu, sum, 1);
        sum += __shfl_xor_sync(0xffffffffu, sum, 2);
        if (part == 0) {
            int n = row;
            g_em[((size_t)t * 8 + b) * 128 + n] = (n < ilen_s) ? sum : 0.f;
            g_tv[((size_t)t * 8 + b) * 128 + n] = pr[160];
        }
    }
}

// ---------------- k_hmm: one warp per batch, shuffle-only ----------------
__global__ __launch_bounds__(32) void k_hmm(
    const int* __restrict__ inputs_len, const int* __restrict__ mel_lens,
    float* __restrict__ out) {
    int b = blockIdx.x, lane = threadIdx.x;
    int ilen = inputs_len[b], mlen = mel_lens[b];
    float la[4];
    float lp = 0.f;
    float* outla = out + 8 + (size_t)b * 256 * 128;
    float emc[4], tvc[4];
#pragma unroll
    for (int q = 0; q < 4; ++q) {
        emc[q] = g_em[(size_t)b * 128 + q * 32 + lane];
        tvc[q] = g_tv[(size_t)b * 128 + q * 32 + lane];
    }
    for (int t = 0; t < T_STEPS; ++t) {
        float emn[4], tvn[4];
        if (t + 1 < T_STEPS) {
#pragma unroll
            for (int q = 0; q < 4; ++q) {
                emn[q] = __ldcg(&g_em[((size_t)(t + 1) * 8 + b) * 128 + q * 32 + lane]);
                tvn[q] = __ldcg(&g_tv[((size_t)(t + 1) * 8 + b) * 128 + q * 32 + lane]);
            }
        }
        float la_t[4];
        if (t == 0) {
#pragma unroll
            for (int q = 0; q < 4; ++q)
                la_t[q] = emc[q] + ((q == 0 && lane == 0) ? 0.f : NEG);
        } else {
            float st_[4], mvv[4];
#pragma unroll
            for (int q = 0; q < 4; ++q) {
                float tv = tvc[q];
                float lstay = logf(fmaxf(1.f / (1.f + expf(tv)), 1e-4f));
                float lmove = logf(fmaxf(1.f / (1.f + expf(-tv)), 1e-4f));
                st_[q] = la[q] + lstay;
                mvv[q] = la[q] + lmove;
            }
            float lv[4];
#pragma unroll
            for (int q = 0; q < 4; ++q)
                lv[q] = __shfl_up_sync(0xffffffffu, mvv[q], 1);
            float c1 = __shfl_sync(0xffffffffu, mvv[0], 31);
            float c2 = __shfl_sync(0xffffffffu, mvv[1], 31);
            float c3 = __shfl_sync(0xffffffffu, mvv[2], 31);
            if (lane == 0) { lv[0] = NEG; lv[1] = c1; lv[2] = c2; lv[3] = c3; }
#pragma unroll
            for (int q = 0; q < 4; ++q) {
                float mx = fmaxf(st_[q], lv[q]);
                float mn = fminf(st_[q], lv[q]);
                float o = mx + log1pf(expf(mn - mx));
                int n = q * 32 + lane;
                o = (n < ilen) ? o : NEG;
                la_t[q] = emc[q] + o;
            }
        }
        float mx = fmaxf(fmaxf(la_t[0], la_t[1]), fmaxf(la_t[2], la_t[3]));
#pragma unroll
        for (int off = 16; off; off >>= 1)
            mx = fmaxf(mx, __shfl_xor_sync(0xffffffffu, mx, off));
        float s = expf(la_t[0] - mx) + expf(la_t[1] - mx) +
                  expf(la_t[2] - mx) + expf(la_t[3] - mx);
#pragma unroll
        for (int off = 16; off; off >>= 1)
            s += __shfl_xor_sync(0xffffffffu, s, off);
        float log_c = mx + logf(s);
#pragma unroll
        for (int q = 0; q < 4; ++q) {
            la[q] = la_t[q] - log_c;
            outla[(size_t)t * 128 + q * 32 + lane] = la[q];
        }
        if (t < mlen) lp += log_c;
#pragma unroll
        for (int q = 0; q < 4; ++q) { emc[q] = emn[q]; tvc[q] = tvn[q]; }
    }
    if (lane == 0) out[b] = lp;
}

// ---------------- launch ----------------
#define GEMM_SMEM (AS_BYTES + 32768)

extern "C" void kernel_launch(void* const* d_in, const int* in_sizes, int n_in,
                              void* d_out, int out_size) {
    const float* inputs = (const float*)d_in[0];
    const float* mels = (const float*)d_in[1];
    const float* pw0 = (const float*)d_in[2];
    const float* pw1 = (const float*)d_in[3];
    const float* wih = (const float*)d_in[4];
    const float* whh = (const float*)d_in[5];
    const float* bih = (const float*)d_in[6];
    const float* bhh = (const float*)d_in[7];
    const float* ow0 = (const float*)d_in[8];
    const float* ob0 = (const float*)d_in[9];
    const float* ow1 = (const float*)d_in[10];
    const float* ob1 = (const float*)d_in[11];
    const float* ow2 = (const float*)d_in[12];
    const float* ob2 = (const float*)d_in[13];
    const int* inputs_len = (const int*)d_in[14];
    const int* mel_lens = (const int*)d_in[15];
    float* out = (float*)d_out;

    cudaFuncSetAttribute(k_scan, cudaFuncAttributeMaxDynamicSharedMemorySize, SCAN_SMEM);
    cudaFuncSetAttribute(k_big, cudaFuncAttributeMaxDynamicSharedMemorySize, BIG_SMEM);
    cudaFuncSetAttribute(k_gemm, cudaFuncAttributeMaxDynamicSharedMemorySize, GEMM_SMEM);

    float *arwin, *w0p, *pre, *base, *hall, *hpart, *gih;
    cudaGetSymbolAddress((void**)&arwin, g_arwin);
    cudaGetSymbolAddress((void**)&w0p, g_w0p);
    cudaGetSymbolAddress((void**)&pre, g_pre);
    cudaGetSymbolAddress((void**)&base, g_base);
    cudaGetSymbolAddress((void**)&hall, g_hall);
    cudaGetSymbolAddress((void**)&hpart, g_hpart);
    cudaGetSymbolAddress((void**)&gih, g_gih);

    k_prep<<<256, 256>>>(mels, pw0, ow1, ow2);
    // p0 = relu(arwin @ w0p^T) -> g_hpart (scratch)
    k_gemm<<<dim3(16, 1), 512, GEMM_SMEM>>>(arwin, 96, 96, w0p, 96, 255, nullptr, nullptr, hpart, 256, 1);
    // pre1 = relu(p0 @ pw1^T) -> g_pre
    k_gemm<<<dim3(16, 1), 512, GEMM_SMEM>>>(hpart, 256, 256, pw1, 256, 255, nullptr, nullptr, pre, 256, 1);
    // gih = pre1 @ wih^T + bih + bhh
    k_gemm<<<dim3(16, 8), 512, GEMM_SMEM>>>(pre, 256, 256, wih, 256, 2047, bih, bhh, gih, 2048, 0);
    // base = inputs @ ow0[:, :512]^T + ob0
    k_gemm<<<dim3(8, 1), 512, GEMM_SMEM>>>(inputs, 512, 512, ow0, 1024, 255, ob0, nullptr, base, 256, 0);
    // LSTM scan
    k_scan<<<64, 256, SCAN_SMEM>>>(whh);
    // hpart = hall @ ow0[:, 512:]^T
    k_gemm<<<dim3(16, 1), 512, GEMM_SMEM>>>(hall, 512, 512, ow0 + 512, 1024, 255, nullptr, nullptr, hpart, 256, 0);
    // fused obs-net + emission: one CTA per (t, batch)
    k_big<<<2048, 512, BIG_SMEM>>>(mels, ob1, ob2, inputs_len);
    // HMM forward
    k_hmm<<<8, 32>>>(inputs_len, mel_lens, out);
}

// round 12
// speedup vs baseline: 1.3969x; 1.1943x over previous
#include <cuda_runtime.h>
#include <cstdint>

#define T_STEPS 256
#define NEG (-1.0e10f)
#define HALF_LOG2PI 0.9189385332046727f
typedef unsigned long long u64;

extern __shared__ char dynsm[];   // single dynamic-smem symbol

// ---------------- global scratch ----------------
__device__ float g_arwin[2048 * 96];
__device__ float g_w0p[256 * 96];
__device__ float g_pre[2048 * 256];
__device__ float g_gih[2048 * 2048];
__device__ float g_base[1024 * 256];
__device__ float g_hall[2048 * 512];
__device__ float g_hpart[2048 * 256];   // also p0 scratch
__device__ float g_hbuf[8192];
__device__ float g_em[2048 * 128];
__device__ float g_tv[2048 * 128];
__device__ float g_ow1t[256 * 256];     // ow1 transposed [k][col], tf32-rounded
__device__ float g_ow2t[256 * 192];     // ow2 transposed [k][col<=192], tf32-rounded, 0-padded
__device__ unsigned g_cnt;
__device__ unsigned g_gen;

// ---------------- helpers ----------------
__device__ __forceinline__ u64 pk2(float x) {
    u64 r; asm("mov.b64 %0, {%1, %1};" : "=l"(r) : "f"(x)); return r;
}
__device__ __forceinline__ u64 pkxy(float x, float y) {
    u64 r; asm("mov.b64 %0, {%1, %2};" : "=l"(r) : "f"(x), "f"(y)); return r;
}
__device__ __forceinline__ void fma2(u64& d, u64 a, u64 b) {
    asm("fma.rn.f32x2 %0, %1, %2, %0;" : "+l"(d) : "l"(a), "l"(b));
}
__device__ __forceinline__ float2 up2(u64 v) {
    float2 f; asm("mov.b64 {%0, %1}, %2;" : "=f"(f.x), "=f"(f.y) : "l"(v)); return f;
}
__device__ __forceinline__ float sigm(float x) { return 1.f / (1.f + expf(-x)); }
__device__ __forceinline__ float tf32r(float x) {
    unsigned u; asm("cvt.rna.tf32.f32 %0, %1;" : "=r"(u) : "f"(x));
    return __uint_as_float(u);
}
__device__ __forceinline__ void mma_tf32(float* d, const unsigned* a,
                                         unsigned b0, unsigned b1) {
    asm("mma.sync.aligned.m16n8k8.row.col.f32.tf32.tf32.f32 "
        "{%0,%1,%2,%3}, {%4,%5,%6,%7}, {%8,%9}, {%0,%1,%2,%3};"
        : "+f"(d[0]), "+f"(d[1]), "+f"(d[2]), "+f"(d[3])
        : "r"(a[0]), "r"(a[1]), "r"(a[2]), "r"(a[3]), "r"(b0), "r"(b1));
}

// epoch grid barrier: monotonic counter, release/acquire
__device__ __forceinline__ void gbar_ep(unsigned target) {
    __syncthreads();
    if (threadIdx.x == 0) {
        unsigned old;
        asm volatile("atom.release.gpu.global.add.u32 %0, [%1], %2;"
                     : "=r"(old) : "l"(&g_cnt), "r"(1u) : "memory");
        if (old + 1u == target) {
            asm volatile("st.release.gpu.global.u32 [%0], %1;"
                         :: "l"(&g_gen), "r"(target) : "memory");
        } else {
            unsigned cur;
            do {
                asm volatile("ld.acquire.gpu.global.u32 %0, [%1];"
                             : "=r"(cur) : "l"(&g_gen) : "memory");
            } while (cur < target);
        }
    }
    __syncthreads();
}

#define AS_LD 132   // f32 stride for k_gemm transposed A tile [32][AS_LD]
#define AS_BYTES (32 * AS_LD * 4)   // 16896

// inner micro step for k_gemm: 8 rows (f32, packed on the fly) x 4 u64-cols
__device__ __forceinline__ void mk_f32(const float* __restrict__ Ak,
                                       const u64* __restrict__ br, u64* acc) {
    float4 a0 = *(const float4*)(Ak);
    float4 a1 = *(const float4*)(Ak + 4);
    u64 b0 = br[0], b1 = br[32], b2 = br[64], b3 = br[96];
    u64 p;
    p = pk2(a0.x); fma2(acc[0], p, b0); fma2(acc[1], p, b1); fma2(acc[2], p, b2); fma2(acc[3], p, b3);
    p = pk2(a0.y); fma2(acc[4], p, b0); fma2(acc[5], p, b1); fma2(acc[6], p, b2); fma2(acc[7], p, b3);
    p = pk2(a0.z); fma2(acc[8], p, b0); fma2(acc[9], p, b1); fma2(acc[10], p, b2); fma2(acc[11], p, b3);
    p = pk2(a0.w); fma2(acc[12], p, b0); fma2(acc[13], p, b1); fma2(acc[14], p, b2); fma2(acc[15], p, b3);
    p = pk2(a1.x); fma2(acc[16], p, b0); fma2(acc[17], p, b1); fma2(acc[18], p, b2); fma2(acc[19], p, b3);
    p = pk2(a1.y); fma2(acc[20], p, b0); fma2(acc[21], p, b1); fma2(acc[22], p, b2); fma2(acc[23], p, b3);
    p = pk2(a1.z); fma2(acc[24], p, b0); fma2(acc[25], p, b1); fma2(acc[26], p, b2); fma2(acc[27], p, b3);
    p = pk2(a1.w); fma2(acc[28], p, b0); fma2(acc[29], p, b1); fma2(acc[30], p, b2); fma2(acc[31], p, b3);
}

// ---------------- k_prep ----------------
__global__ __launch_bounds__(256) void k_prep(const float* __restrict__ mels,
                                              const float* __restrict__ w0,
                                              const float* __restrict__ ow1,
                                              const float* __restrict__ ow2) {
    int i0 = blockIdx.x * 256 + threadIdx.x;
    int stride = gridDim.x * 256;
    if (i0 == 0) { g_cnt = 0; g_gen = 0; }
    for (int e = i0; e < 2048 * 96; e += stride) {
        int r = e / 96, k = e - r * 96;
        int t = r >> 3, b = r & 7;
        g_arwin[e] = (k < 80 && t > 0) ? mels[((size_t)b * 80 + k) * 256 + t - 1] : 0.f;
    }
    for (int e = i0; e < 256 * 96; e += stride) {
        int c = e / 96, k = e - c * 96;
        g_w0p[e] = (k < 80) ? w0[c * 80 + k] : 0.f;
    }
    for (int e = i0; e < 65536; e += stride) {   // ow1 transposed, tf32-rounded
        int k = e >> 8, c = e & 255;
        g_ow1t[e] = tf32r(ow1[c * 256 + k]);
    }
    for (int e = i0; e < 49152; e += stride) {   // ow2 transposed, tf32-rounded, padded
        int k = e / 192, c = e - k * 192;
        g_ow2t[e] = (c < 161) ? tf32r(ow2[c * 256 + k]) : 0.f;
    }
}

// ---------------- generic GEMM: 128x256 tile, 512 thr, fp32 f32x2, prefetched ----------------
__global__ __launch_bounds__(512) void k_gemm(
    const float* __restrict__ A, int lda, int K,
    const float* __restrict__ W, int ldw, int wmax,
    const float* __restrict__ b1, const float* __restrict__ b2,
    float* __restrict__ C, int ldc, int relu) {
    float* As = (float*)dynsm;
    u64* Bs = (u64*)(dynsm + AS_BYTES);
    int tid = threadIdx.x, w = tid >> 5, lane = tid & 31;
    int r0 = blockIdx.x * 128, c0 = blockIdx.y * 256;
    u64 acc[32];
#pragma unroll
    for (int i = 0; i < 32; ++i) acc[i] = 0ull;
    int ar = tid & 127, kq = (tid >> 7) * 8;
    const float* Arow = A + (size_t)(r0 + ar) * lda + kq;
    int bp = tid & 127;
    int ca = c0 + (bp & 31) + 64 * (bp >> 5);
    int cb = ca + 32;
    if (ca > wmax) ca = wmax;
    if (cb > wmax) cb = wmax;
    const float* wa = W + (size_t)ca * ldw + kq;
    const float* wb = W + (size_t)cb * ldw + kq;
    int nch = K >> 5;

    float4 pa0 = *(const float4*)(Arow);
    float4 pa1 = *(const float4*)(Arow + 4);
    float4 qa0 = *(const float4*)(wa);
    float4 qa1 = *(const float4*)(wa + 4);
    float4 qb0 = *(const float4*)(wb);
    float4 qb1 = *(const float4*)(wb + 4);

    for (int ch = 0; ch < nch; ++ch) {
        if (ch) __syncthreads();
        {
            float* ap = As + kq * AS_LD + ar;
            ap[0 * AS_LD] = pa0.x; ap[1 * AS_LD] = pa0.y;
            ap[2 * AS_LD] = pa0.z; ap[3 * AS_LD] = pa0.w;
            ap[4 * AS_LD] = pa1.x; ap[5 * AS_LD] = pa1.y;
            ap[6 * AS_LD] = pa1.z; ap[7 * AS_LD] = pa1.w;
        }
        {
            u64* dst = Bs + kq * 128 + bp;
            dst[0 * 128] = pkxy(qa0.x, qb0.x); dst[1 * 128] = pkxy(qa0.y, qb0.y);
            dst[2 * 128] = pkxy(qa0.z, qb0.z); dst[3 * 128] = pkxy(qa0.w, qb0.w);
            dst[4 * 128] = pkxy(qa1.x, qb1.x); dst[5 * 128] = pkxy(qa1.y, qb1.y);
            dst[6 * 128] = pkxy(qa1.z, qb1.z); dst[7 * 128] = pkxy(qa1.w, qb1.w);
        }
        __syncthreads();
        if (ch + 1 < nch) {
            int k0 = (ch + 1) * 32;
            pa0 = *(const float4*)(Arow + k0);
            pa1 = *(const float4*)(Arow + k0 + 4);
            qa0 = *(const float4*)(wa + k0);
            qa1 = *(const float4*)(wa + k0 + 4);
            qb0 = *(const float4*)(wb + k0);
            qb1 = *(const float4*)(wb + k0 + 4);
        }
#pragma unroll 8
        for (int kk = 0; kk < 32; ++kk)
            mk_f32(As + kk * AS_LD + w * 8, Bs + kk * 128 + lane, acc);
    }
    float bxa[4], bxb[4];
#pragma unroll
    for (int j = 0; j < 4; ++j) {
        int c = c0 + lane + 64 * j;
        bxa[j] = (b1 ? b1[c] : 0.f) + (b2 ? b2[c] : 0.f);
        bxb[j] = (b1 ? b1[c + 32] : 0.f) + (b2 ? b2[c + 32] : 0.f);
    }
#pragma unroll
    for (int i = 0; i < 8; ++i) {
        float* cr = C + (size_t)(r0 + w * 8 + i) * ldc + c0;
#pragma unroll
        for (int j = 0; j < 4; ++j) {
            float2 v = up2(acc[i * 4 + j]);
            float x = v.x + bxa[j], y = v.y + bxb[j];
            if (relu) { x = fmaxf(x, 0.f); y = fmaxf(y, 0.f); }
            cr[lane + 64 * j] = x;
            cr[lane + 64 * j + 32] = y;
        }
    }
}

// ---------------- k_scan: LSTM recurrence (unchanged, verified) ----------------
#define SCAN_SMEM ((32 + 8) * 516 * 4)
__global__ __launch_bounds__(256) void k_scan(const float* __restrict__ whh) {
    float* wsm = (float*)dynsm;
    float* hs = (float*)dynsm + 32 * 516;
    int tid = threadIdx.x, cta = blockIdx.x;
    int mbase = cta * 8;
    {
        int rowid = tid >> 3, seg = tid & 7;
        int g = rowid & 3, ml = rowid >> 2;
        const float* src = whh + (size_t)(g * 512 + mbase + ml) * 512 + seg * 64;
        float* dst = wsm + rowid * 516 + seg * 64;
#pragma unroll
        for (int q = 0; q < 64; q += 4) *(float4*)(dst + q) = *(const float4*)(src + q);
    }
    int gt = cta * 256 + tid;
    if (gt < 8192) g_hbuf[gt] = 0.f;

    int b = tid & 7, gate = (tid >> 3) & 3, ml = tid >> 5;
    int m = mbase + ml;
    float cst = 0.f;
    unsigned epoch = 1;
    gbar_ep(epoch * 64);

    int cur = 0;
    for (int t = 0; t < T_STEPS; ++t) {
        float gihv0 = 0.f, gihv1 = 0.f, gihv2 = 0.f, gihv3 = 0.f;
        if (gate == 0) {
            const float* gp = g_gih + ((size_t)t * 8 + b) * 2048 + m;
            gihv0 = __ldg(gp); gihv1 = __ldg(gp + 512);
            gihv2 = __ldg(gp + 1024); gihv3 = __ldg(gp + 1536);
        }
        {
            int bb = tid >> 5, k0 = (tid & 31) * 16;
            const float4* src = (const float4*)(g_hbuf + cur * 4096 + bb * 512 + k0);
            float* dst = hs + bb * 516 + k0;
#pragma unroll
            for (int q = 0; q < 4; ++q) *(float4*)(dst + q * 4) = __ldcg(src + q);
        }
        __syncthreads();
        u64 acc = 0ull;
        const float* wr = wsm + (ml * 4 + gate) * 516;
        const float* hr = hs + b * 516;
#pragma unroll 8
        for (int k = 0; k < 512; k += 8) {
            ulonglong2 wa = *(const ulonglong2*)(wr + k);
            ulonglong2 wb = *(const ulonglong2*)(wr + k + 4);
            ulonglong2 ha = *(const ulonglong2*)(hr + k);
            ulonglong2 hb = *(const ulonglong2*)(hr + k + 4);
            fma2(acc, wa.x, ha.x); fma2(acc, wa.y, ha.y);
            fma2(acc, wb.x, hb.x); fma2(acc, wb.y, hb.y);
        }
        float2 dv = up2(acc);
        float dot = dv.x + dv.y;
        int lb = tid & 7;
        float d0 = __shfl_sync(0xffffffffu, dot, lb + 0);
        float d1 = __shfl_sync(0xffffffffu, dot, lb + 8);
        float d2 = __shfl_sync(0xffffffffu, dot, lb + 16);
        float d3 = __shfl_sync(0xffffffffu, dot, lb + 24);
        if (gate == 0) {
            float gi = gihv0 + d0, gf = gihv1 + d1, gg = gihv2 + d2, go = gihv3 + d3;
            float cn = sigm(gf) * cst + sigm(gi) * tanhf(gg);
            float hn = sigm(go) * tanhf(cn);
            cst = cn;
            __stcg(&g_hbuf[(cur ^ 1) * 4096 + b * 512 + m], hn);
            g_hall[((size_t)t * 8 + b) * 512 + m] = hn;
        }
        cur ^= 1;
        epoch++;
        gbar_ep(epoch * 64);
    }
}

// ---------------- k_big: tf32 mma obs-net + emission, one CTA per (t, batch) ----------------
// 512 thr = 16 warps (4x4 warp grid). Warp tile: 32 rows x 64 cols (s1) / 32 x 48 (s2).
#define LDA 140      // = 12 mod 32: conflict-free for frag loads AND transposed a2 writes
#define LDB1 264     // = 8 mod 32
#define LDB2 200     // = 8 mod 32
#define A2ST_BYTES (256 * LDA * 4)           // 143360
#define AS1_BYTES (32 * LDA * 4)             // 17920
#define BIG_SMEM (A2ST_BYTES + AS1_BYTES + 32 * LDB1 * 4)   // 195072
__global__ __launch_bounds__(512) void k_big(
    const float* __restrict__ mels, const float* __restrict__ ob1,
    const float* __restrict__ ob2, const int* __restrict__ inputs_len) {
    float* a2st = (float*)dynsm;                         // [256][LDA] a2 transposed
    float* As = (float*)(dynsm + A2ST_BYTES);            // [32][LDA] a1 chunk transposed
    float* Bs = (float*)(dynsm + A2ST_BYTES + AS1_BYTES);// [32][LDB1] (s2: [32][LDB2])
    const unsigned* a2stu = (const unsigned*)a2st;
    const unsigned* Asu = (const unsigned*)As;
    const unsigned* Bsu = (const unsigned*)Bs;
    __shared__ float xs[80];
    __shared__ int ilen_s;
    int tid = threadIdx.x, w = tid >> 5, lane = tid & 31;
    int gid = lane >> 2, tig = lane & 3;
    int bid = blockIdx.x;
    int b = bid & 7, t = bid >> 3;
    int r0 = b * 128;
    int mrow = (w >> 2) * 32;
    int nc1 = (w & 3) * 64;
    int nc2 = (w & 3) * 48;

    if (tid < 80) xs[tid] = mels[((size_t)b * 80 + tid) * 256 + t];
    if (tid == 80) ilen_s = inputs_len[b];

    int ar = tid & 127, kq = (tid >> 7) * 8;
    const float* bp_ = g_base + (size_t)(r0 + ar) * 256 + kq;
    const float* hp_ = g_hpart + ((size_t)t * 8 + b) * 256 + kq;
    int kkf = tid >> 4, segf = tid & 15;   // B-fill mapping: 32 k x 16 segs

    // ---- stage 1: a2 = relu(a1 @ ow1^T + ob1) ----
    float d1[64];
#pragma unroll
    for (int i = 0; i < 64; ++i) d1[i] = 0.f;
    for (int ch = 0; ch < 8; ++ch) {
        int k0 = ch * 32;
        if (ch) __syncthreads();
        {   // fill A chunk: a1 = relu(base + hpart), tf32-rounded, [k][row]
            float4 v0 = *(const float4*)(bp_ + k0);
            float4 v1 = *(const float4*)(bp_ + k0 + 4);
            float4 h0 = *(const float4*)(hp_ + k0);
            float4 h1 = *(const float4*)(hp_ + k0 + 4);
            float* ap = As + kq * LDA + ar;
            ap[0 * LDA] = tf32r(fmaxf(v0.x + h0.x, 0.f));
            ap[1 * LDA] = tf32r(fmaxf(v0.y + h0.y, 0.f));
            ap[2 * LDA] = tf32r(fmaxf(v0.z + h0.z, 0.f));
            ap[3 * LDA] = tf32r(fmaxf(v0.w + h0.w, 0.f));
            ap[4 * LDA] = tf32r(fmaxf(v1.x + h1.x, 0.f));
            ap[5 * LDA] = tf32r(fmaxf(v1.y + h1.y, 0.f));
            ap[6 * LDA] = tf32r(fmaxf(v1.z + h1.z, 0.f));
            ap[7 * LDA] = tf32r(fmaxf(v1.w + h1.w, 0.f));
        }
        {   // fill B chunk: straight copy of pre-transposed ow1t
            const float4* src = (const float4*)(g_ow1t + (size_t)(k0 + kkf) * 256 + segf * 16);
            float4* dst = (float4*)(Bs + kkf * LDB1 + segf * 16);
            dst[0] = src[0]; dst[1] = src[1]; dst[2] = src[2]; dst[3] = src[3];
        }
        __syncthreads();
#pragma unroll
        for (int s8 = 0; s8 < 4; ++s8) {
            int kr0 = (s8 * 8 + tig) * LDA, kr4 = (s8 * 8 + tig + 4) * LDA;
            unsigned a0[4], a1f[4];
            a0[0] = Asu[kr0 + mrow + gid];       a0[1] = Asu[kr0 + mrow + gid + 8];
            a0[2] = Asu[kr4 + mrow + gid];       a0[3] = Asu[kr4 + mrow + gid + 8];
            a1f[0] = Asu[kr0 + mrow + 16 + gid]; a1f[1] = Asu[kr0 + mrow + 16 + gid + 8];
            a1f[2] = Asu[kr4 + mrow + 16 + gid]; a1f[3] = Asu[kr4 + mrow + 16 + gid + 8];
            int kb0 = (s8 * 8 + tig) * LDB1, kb4 = (s8 * 8 + tig + 4) * LDB1;
#pragma unroll
            for (int nt = 0; nt < 8; ++nt) {
                unsigned b0 = Bsu[kb0 + nc1 + nt * 8 + gid];
                unsigned b1 = Bsu[kb4 + nc1 + nt * 8 + gid];
                mma_tf32(d1 + nt * 4, a0, b0, b1);
                mma_tf32(d1 + 32 + nt * 4, a1f, b0, b1);
            }
        }
    }
    __syncthreads();
    {   // write a2 transposed [col][row] with bias+relu, tf32-rounded
#pragma unroll
        for (int mt = 0; mt < 2; ++mt) {
            int rw = mrow + mt * 16 + gid;
#pragma unroll
            for (int nt = 0; nt < 8; ++nt) {
                int cA = nc1 + nt * 8 + 2 * tig;
                float bA = __ldg(ob1 + cA), bB = __ldg(ob1 + cA + 1);
                const float* dd = d1 + mt * 32 + nt * 4;
                a2st[cA * LDA + rw] = tf32r(fmaxf(dd[0] + bA, 0.f));
                a2st[(cA + 1) * LDA + rw] = tf32r(fmaxf(dd[1] + bB, 0.f));
                a2st[cA * LDA + rw + 8] = tf32r(fmaxf(dd[2] + bA, 0.f));
                a2st[(cA + 1) * LDA + rw + 8] = tf32r(fmaxf(dd[3] + bB, 0.f));
            }
        }
    }
    __syncthreads();
    // ---- stage 2: p = a2 @ ow2^T + ob2 (161 cols via 192) ----
    float d2[48];
#pragma unroll
    for (int i = 0; i < 48; ++i) d2[i] = 0.f;
    for (int ch = 0; ch < 8; ++ch) {
        int k0 = ch * 32;
        if (ch) __syncthreads();
        if (segf < 12) {   // fill B chunk from ow2t
            const float4* src = (const float4*)(g_ow2t + (size_t)(k0 + kkf) * 192 + segf * 16);
            float4* dst = (float4*)(Bs + kkf * LDB2 + segf * 16);
            dst[0] = src[0]; dst[1] = src[1]; dst[2] = src[2]; dst[3] = src[3];
        }
        __syncthreads();
#pragma unroll
        for (int s8 = 0; s8 < 4; ++s8) {
            int kr0 = (k0 + s8 * 8 + tig) * LDA, kr4 = (k0 + s8 * 8 + tig + 4) * LDA;
            unsigned a0[4], a1f[4];
            a0[0] = a2stu[kr0 + mrow + gid];       a0[1] = a2stu[kr0 + mrow + gid + 8];
            a0[2] = a2stu[kr4 + mrow + gid];       a0[3] = a2stu[kr4 + mrow + gid + 8];
            a1f[0] = a2stu[kr0 + mrow + 16 + gid]; a1f[1] = a2stu[kr0 + mrow + 16 + gid + 8];
            a1f[2] = a2stu[kr4 + mrow + 16 + gid]; a1f[3] = a2stu[kr4 + mrow + 16 + gid + 8];
            int kb0 = (s8 * 8 + tig) * LDB2, kb4 = (s8 * 8 + tig + 4) * LDB2;
#pragma unroll
            for (int nt = 0; nt < 6; ++nt) {
                unsigned b0 = Bsu[kb0 + nc2 + nt * 8 + gid];
                unsigned b1 = Bsu[kb4 + nc2 + nt * 8 + gid];
                mma_tf32(d2 + nt * 4, a0, b0, b1);
                mma_tf32(d2 + 24 + nt * 4, a1f, b0, b1);
            }
        }
    }
    __syncthreads();
    float* ps = a2st;   // overlay [128][164]
    {
#pragma unroll
        for (int mt = 0; mt < 2; ++mt) {
            int rw = mrow + mt * 16 + gid;
#pragma unroll
            for (int nt = 0; nt < 6; ++nt) {
                int cA = nc2 + nt * 8 + 2 * tig, cB = cA + 1;
                const float* dd = d2 + mt * 24 + nt * 4;
                if (cA < 161) {
                    float bb = __ldg(ob2 + cA);
                    ps[rw * 164 + cA] = dd[0] + bb;
                    ps[(rw + 8) * 164 + cA] = dd[2] + bb;
                }
                if (cB < 161) {
                    float bb = __ldg(ob2 + cB);
                    ps[rw * 164 + cB] = dd[1] + bb;
                    ps[(rw + 8) * 164 + cB] = dd[3] + bb;
                }
            }
        }
    }
    __syncthreads();
    {   // emission: warp w -> rows w*8..+8; 4 lanes per row, 20 d's each
        int ri = lane >> 2, part = lane & 3;
        int row = w * 8 + ri;
        const float* pr = ps + row * 164;
        float sum = 0.f;
        int d0 = part * 20;
        for (int d = d0; d < d0 + 20; ++d) {
            float mean = pr[d], sh = pr[80 + d];
            float stdv = fmaxf(sh, 0.f) + log1pf(expf(-fabsf(sh))) + 1e-3f;
            float z = (xs[d] - mean) / stdv;
            sum += -0.5f * z * z - logf(stdv) - HALF_LOG2PI;
        }
        sum += __shfl_xor_sync(0xffffffffu, sum, 1);
        sum += __shfl_xor_sync(0xffffffffu, sum, 2);
        if (part == 0) {
            int n = row;
            g_em[((size_t)t * 8 + b) * 128 + n] = (n < ilen_s) ? sum : 0.f;
            g_tv[((size_t)t * 8 + b) * 128 + n] = pr[160];
        }
    }
}

// ---------------- k_hmm: one warp per batch, shuffle-only ----------------
__global__ __launch_bounds__(32) void k_hmm(
    const int* __restrict__ inputs_len, const int* __restrict__ mel_lens,
    float* __restrict__ out) {
    int b = blockIdx.x, lane = threadIdx.x;
    int ilen = inputs_len[b], mlen = mel_lens[b];
    float la[4];
    float lp = 0.f;
    float* outla = out + 8 + (size_t)b * 256 * 128;
    float emc[4], tvc[4];
#pragma unroll
    for (int q = 0; q < 4; ++q) {
        emc[q] = g_em[(size_t)b * 128 + q * 32 + lane];
        tvc[q] = g_tv[(size_t)b * 128 + q * 32 + lane];
    }
    for (int t = 0; t < T_STEPS; ++t) {
        float emn[4], tvn[4];
        if (t + 1 < T_STEPS) {
#pragma unroll
            for (int q = 0; q < 4; ++q) {
                emn[q] = __ldcg(&g_em[((size_t)(t + 1) * 8 + b) * 128 + q * 32 + lane]);
                tvn[q] = __ldcg(&g_tv[((size_t)(t + 1) * 8 + b) * 128 + q * 32 + lane]);
            }
        }
        float la_t[4];
        if (t == 0) {
#pragma unroll
            for (int q = 0; q < 4; ++q)
                la_t[q] = emc[q] + ((q == 0 && lane == 0) ? 0.f : NEG);
        } else {
            float st_[4], mvv[4];
#pragma unroll
            for (int q = 0; q < 4; ++q) {
                float tv = tvc[q];
                float lstay = logf(fmaxf(1.f / (1.f + expf(tv)), 1e-4f));
                float lmove = logf(fmaxf(1.f / (1.f + expf(-tv)), 1e-4f));
                st_[q] = la[q] + lstay;
                mvv[q] = la[q] + lmove;
            }
            float lv[4];
#pragma unroll
            for (int q = 0; q < 4; ++q)
                lv[q] = __shfl_up_sync(0xffffffffu, mvv[q], 1);
            float c1 = __shfl_sync(0xffffffffu, mvv[0], 31);
            float c2 = __shfl_sync(0xffffffffu, mvv[1], 31);
            float c3 = __shfl_sync(0xffffffffu, mvv[2], 31);
            if (lane == 0) { lv[0] = NEG; lv[1] = c1; lv[2] = c2; lv[3] = c3; }
#pragma unroll
            for (int q = 0; q < 4; ++q) {
                float mx = fmaxf(st_[q], lv[q]);
                float mn = fminf(st_[q], lv[q]);
                float o = mx + log1pf(expf(mn - mx));
                int n = q * 32 + lane;
                o = (n < ilen) ? o : NEG;
                la_t[q] = emc[q] + o;
            }
        }
        float mx = fmaxf(fmaxf(la_t[0], la_t[1]), fmaxf(la_t[2], la_t[3]));
#pragma unroll
        for (int off = 16; off; off >>= 1)
            mx = fmaxf(mx, __shfl_xor_sync(0xffffffffu, mx, off));
        float s = expf(la_t[0] - mx) + expf(la_t[1] - mx) +
                  expf(la_t[2] - mx) + expf(la_t[3] - mx);
#pragma unroll
        for (int off = 16; off; off >>= 1)
            s += __shfl_xor_sync(0xffffffffu, s, off);
        float log_c = mx + logf(s);
#pragma unroll
        for (int q = 0; q < 4; ++q) {
            la[q] = la_t[q] - log_c;
            outla[(size_t)t * 128 + q * 32 + lane] = la[q];
        }
        if (t < mlen) lp += log_c;
#pragma unroll
        for (int q = 0; q < 4; ++q) { emc[q] = emn[q]; tvc[q] = tvn[q]; }
    }
    if (lane == 0) out[b] = lp;
}

// ---------------- launch ----------------
#define GEMM_SMEM (AS_BYTES + 32768)

extern "C" void kernel_launch(void* const* d_in, const int* in_sizes, int n_in,
                              void* d_out, int out_size) {
    const float* inputs = (const float*)d_in[0];
    const float* mels = (const float*)d_in[1];
    const float* pw0 = (const float*)d_in[2];
    const float* pw1 = (const float*)d_in[3];
    const float* wih = (const float*)d_in[4];
    const float* whh = (const float*)d_in[5];
    const float* bih = (const float*)d_in[6];
    const float* bhh = (const float*)d_in[7];
    const float* ow0 = (const float*)d_in[8];
    const float* ob0 = (const float*)d_in[9];
    const float* ow1 = (const float*)d_in[10];
    const float* ob1 = (const float*)d_in[11];
    const float* ow2 = (const float*)d_in[12];
    const float* ob2 = (const float*)d_in[13];
    const int* inputs_len = (const int*)d_in[14];
    const int* mel_lens = (const int*)d_in[15];
    float* out = (float*)d_out;

    cudaFuncSetAttribute(k_scan, cudaFuncAttributeMaxDynamicSharedMemorySize, SCAN_SMEM);
    cudaFuncSetAttribute(k_big, cudaFuncAttributeMaxDynamicSharedMemorySize, BIG_SMEM);
    cudaFuncSetAttribute(k_gemm, cudaFuncAttributeMaxDynamicSharedMemorySize, GEMM_SMEM);

    float *arwin, *w0p, *pre, *base, *hall, *hpart, *gih;
    cudaGetSymbolAddress((void**)&arwin, g_arwin);
    cudaGetSymbolAddress((void**)&w0p, g_w0p);
    cudaGetSymbolAddress((void**)&pre, g_pre);
    cudaGetSymbolAddress((void**)&base, g_base);
    cudaGetSymbolAddress((void**)&hall, g_hall);
    cudaGetSymbolAddress((void**)&hpart, g_hpart);
    cudaGetSymbolAddress((void**)&gih, g_gih);

    k_prep<<<256, 256>>>(mels, pw0, ow1, ow2);
    // p0 = relu(arwin @ w0p^T) -> g_hpart (scratch)
    k_gemm<<<dim3(16, 1), 512, GEMM_SMEM>>>(arwin, 96, 96, w0p, 96, 255, nullptr, nullptr, hpart, 256, 1);
    // pre1 = relu(p0 @ pw1^T) -> g_pre
    k_gemm<<<dim3(16, 1), 512, GEMM_SMEM>>>(hpart, 256, 256, pw1, 256, 255, nullptr, nullptr, pre, 256, 1);
    // gih = pre1 @ wih^T + bih + bhh
    k_gemm<<<dim3(16, 8), 512, GEMM_SMEM>>>(pre, 256, 256, wih, 256, 2047, bih, bhh, gih, 2048, 0);
    // base = inputs @ ow0[:, :512]^T + ob0
    k_gemm<<<dim3(8, 1), 512, GEMM_SMEM>>>(inputs, 512, 512, ow0, 1024, 255, ob0, nullptr, base, 256, 0);
    // LSTM scan
    k_scan<<<64, 256, SCAN_SMEM>>>(whh);
    // hpart = hall @ ow0[:, 512:]^T
    k_gemm<<<dim3(16, 1), 512, GEMM_SMEM>>>(hall, 512, 512, ow0 + 512, 1024, 255, nullptr, nullptr, hpart, 256, 0);
    // fused obs-net + emission (tf32 tensor cores): one CTA per (t, batch)
    k_big<<<2048, 512, BIG_SMEM>>>(mels, ob1, ob2, inputs_len);
    // HMM forward
    k_hmm<<<8, 32>>>(inputs_len, mel_lens, out);
}

// round 13
// speedup vs baseline: 1.5837x; 1.1338x over previous
#include <cuda_runtime.h>
#include <cstdint>

#define T_STEPS 256
#define NEG (-1.0e10f)
#define HALF_LOG2PI 0.9189385332046727f
typedef unsigned long long u64;

extern __shared__ char dynsm[];   // single dynamic-smem symbol

// ---------------- global scratch ----------------
__device__ float g_arwin[2048 * 96];
__device__ float g_w0p[256 * 96];
__device__ float g_pre[2048 * 256];
__device__ float g_gih[2048 * 2048];
__device__ float g_base[1024 * 256];
__device__ float g_hall[2048 * 512];
__device__ float g_hpart[2048 * 256];   // also p0 scratch
__device__ float g_hbuf[8192];
__device__ float g_em[2048 * 128];
__device__ float g_tv[2048 * 128];
__device__ unsigned g_ow1b[128 * 256];  // ow1 bf16x2-packed [kpair][col]
__device__ unsigned g_ow2b[128 * 192];  // ow2 bf16x2-packed [kpair][col<192], 0-padded
__device__ unsigned g_cnt;
__device__ unsigned g_gen;

// ---------------- helpers ----------------
__device__ __forceinline__ u64 pk2(float x) {
    u64 r; asm("mov.b64 %0, {%1, %1};" : "=l"(r) : "f"(x)); return r;
}
__device__ __forceinline__ u64 pkxy(float x, float y) {
    u64 r; asm("mov.b64 %0, {%1, %2};" : "=l"(r) : "f"(x), "f"(y)); return r;
}
__device__ __forceinline__ void fma2(u64& d, u64 a, u64 b) {
    asm("fma.rn.f32x2 %0, %1, %2, %0;" : "+l"(d) : "l"(a), "l"(b));
}
__device__ __forceinline__ float2 up2(u64 v) {
    float2 f; asm("mov.b64 {%0, %1}, %2;" : "=f"(f.x), "=f"(f.y) : "l"(v)); return f;
}
__device__ __forceinline__ float sigm(float x) { return 1.f / (1.f + expf(-x)); }
// pack two f32 into bf16x2: lo = first arg (even k), hi = second (odd k)
__device__ __forceinline__ unsigned pkbf(float lo, float hi) {
    unsigned r; asm("cvt.rn.bf16x2.f32 %0, %1, %2;" : "=r"(r) : "f"(hi), "f"(lo));
    return r;
}
__device__ __forceinline__ void mma_bf16(float* d, const unsigned* a,
                                         unsigned b0, unsigned b1) {
    asm("mma.sync.aligned.m16n8k16.row.col.f32.bf16.bf16.f32 "
        "{%0,%1,%2,%3}, {%4,%5,%6,%7}, {%8,%9}, {%0,%1,%2,%3};"
        : "+f"(d[0]), "+f"(d[1]), "+f"(d[2]), "+f"(d[3])
        : "r"(a[0]), "r"(a[1]), "r"(a[2]), "r"(a[3]), "r"(b0), "r"(b1));
}

// epoch grid barrier: monotonic counter, release/acquire
__device__ __forceinline__ void gbar_ep(unsigned target) {
    __syncthreads();
    if (threadIdx.x == 0) {
        unsigned old;
        asm volatile("atom.release.gpu.global.add.u32 %0, [%1], %2;"
                     : "=r"(old) : "l"(&g_cnt), "r"(1u) : "memory");
        if (old + 1u == target) {
            asm volatile("st.release.gpu.global.u32 [%0], %1;"
                         :: "l"(&g_gen), "r"(target) : "memory");
        } else {
            unsigned cur;
            do {
                asm volatile("ld.acquire.gpu.global.u32 %0, [%1];"
                             : "=r"(cur) : "l"(&g_gen) : "memory");
            } while (cur < target);
        }
    }
    __syncthreads();
}

#define AS_LD 132   // f32 stride for k_gemm transposed A tile [32][AS_LD]
#define AS_BYTES (32 * AS_LD * 4)   // 16896

// inner micro step for k_gemm: 8 rows (f32, packed on the fly) x 4 u64-cols
__device__ __forceinline__ void mk_f32(const float* __restrict__ Ak,
                                       const u64* __restrict__ br, u64* acc) {
    float4 a0 = *(const float4*)(Ak);
    float4 a1 = *(const float4*)(Ak + 4);
    u64 b0 = br[0], b1 = br[32], b2 = br[64], b3 = br[96];
    u64 p;
    p = pk2(a0.x); fma2(acc[0], p, b0); fma2(acc[1], p, b1); fma2(acc[2], p, b2); fma2(acc[3], p, b3);
    p = pk2(a0.y); fma2(acc[4], p, b0); fma2(acc[5], p, b1); fma2(acc[6], p, b2); fma2(acc[7], p, b3);
    p = pk2(a0.z); fma2(acc[8], p, b0); fma2(acc[9], p, b1); fma2(acc[10], p, b2); fma2(acc[11], p, b3);
    p = pk2(a0.w); fma2(acc[12], p, b0); fma2(acc[13], p, b1); fma2(acc[14], p, b2); fma2(acc[15], p, b3);
    p = pk2(a1.x); fma2(acc[16], p, b0); fma2(acc[17], p, b1); fma2(acc[18], p, b2); fma2(acc[19], p, b3);
    p = pk2(a1.y); fma2(acc[20], p, b0); fma2(acc[21], p, b1); fma2(acc[22], p, b2); fma2(acc[23], p, b3);
    p = pk2(a1.z); fma2(acc[24], p, b0); fma2(acc[25], p, b1); fma2(acc[26], p, b2); fma2(acc[27], p, b3);
    p = pk2(a1.w); fma2(acc[28], p, b0); fma2(acc[29], p, b1); fma2(acc[30], p, b2); fma2(acc[31], p, b3);
}

// ---------------- k_prep ----------------
__global__ __launch_bounds__(256) void k_prep(const float* __restrict__ mels,
                                              const float* __restrict__ w0,
                                              const float* __restrict__ ow1,
                                              const float* __restrict__ ow2) {
    int i0 = blockIdx.x * 256 + threadIdx.x;
    int stride = gridDim.x * 256;
    if (i0 == 0) { g_cnt = 0; g_gen = 0; }
    for (int e = i0; e < 2048 * 96; e += stride) {
        int r = e / 96, k = e - r * 96;
        int t = r >> 3, b = r & 7;
        g_arwin[e] = (k < 80 && t > 0) ? mels[((size_t)b * 80 + k) * 256 + t - 1] : 0.f;
    }
    for (int e = i0; e < 256 * 96; e += stride) {
        int c = e / 96, k = e - c * 96;
        g_w0p[e] = (k < 80) ? w0[c * 80 + k] : 0.f;
    }
    for (int e = i0; e < 32768; e += stride) {   // ow1 bf16-pack [kp][col]
        int kp = e >> 8, c = e & 255;
        g_ow1b[e] = pkbf(ow1[c * 256 + 2 * kp], ow1[c * 256 + 2 * kp + 1]);
    }
    for (int e = i0; e < 24576; e += stride) {   // ow2 bf16-pack [kp][col], padded
        int kp = e / 192, c = e - kp * 192;
        g_ow2b[e] = (c < 161) ? pkbf(ow2[c * 256 + 2 * kp], ow2[c * 256 + 2 * kp + 1]) : 0u;
    }
}

// ---------------- generic GEMM: 128x256 tile, 512 thr, fp32 f32x2, prefetched ----------------
__global__ __launch_bounds__(512) void k_gemm(
    const float* __restrict__ A, int lda, int K,
    const float* __restrict__ W, int ldw, int wmax,
    const float* __restrict__ b1, const float* __restrict__ b2,
    float* __restrict__ C, int ldc, int relu) {
    float* As = (float*)dynsm;
    u64* Bs = (u64*)(dynsm + AS_BYTES);
    int tid = threadIdx.x, w = tid >> 5, lane = tid & 31;
    int r0 = blockIdx.x * 128, c0 = blockIdx.y * 256;
    u64 acc[32];
#pragma unroll
    for (int i = 0; i < 32; ++i) acc[i] = 0ull;
    int ar = tid & 127, kq = (tid >> 7) * 8;
    const float* Arow = A + (size_t)(r0 + ar) * lda + kq;
    int bp = tid & 127;
    int ca = c0 + (bp & 31) + 64 * (bp >> 5);
    int cb = ca + 32;
    if (ca > wmax) ca = wmax;
    if (cb > wmax) cb = wmax;
    const float* wa = W + (size_t)ca * ldw + kq;
    const float* wb = W + (size_t)cb * ldw + kq;
    int nch = K >> 5;

    float4 pa0 = *(const float4*)(Arow);
    float4 pa1 = *(const float4*)(Arow + 4);
    float4 qa0 = *(const float4*)(wa);
    float4 qa1 = *(const float4*)(wa + 4);
    float4 qb0 = *(const float4*)(wb);
    float4 qb1 = *(const float4*)(wb + 4);

    for (int ch = 0; ch < nch; ++ch) {
        if (ch) __syncthreads();
        {
            float* ap = As + kq * AS_LD + ar;
            ap[0 * AS_LD] = pa0.x; ap[1 * AS_LD] = pa0.y;
            ap[2 * AS_LD] = pa0.z; ap[3 * AS_LD] = pa0.w;
            ap[4 * AS_LD] = pa1.x; ap[5 * AS_LD] = pa1.y;
            ap[6 * AS_LD] = pa1.z; ap[7 * AS_LD] = pa1.w;
        }
        {
            u64* dst = Bs + kq * 128 + bp;
            dst[0 * 128] = pkxy(qa0.x, qb0.x); dst[1 * 128] = pkxy(qa0.y, qb0.y);
            dst[2 * 128] = pkxy(qa0.z, qb0.z); dst[3 * 128] = pkxy(qa0.w, qb0.w);
            dst[4 * 128] = pkxy(qa1.x, qb1.x); dst[5 * 128] = pkxy(qa1.y, qb1.y);
            dst[6 * 128] = pkxy(qa1.z, qb1.z); dst[7 * 128] = pkxy(qa1.w, qb1.w);
        }
        __syncthreads();
        if (ch + 1 < nch) {
            int k0 = (ch + 1) * 32;
            pa0 = *(const float4*)(Arow + k0);
            pa1 = *(const float4*)(Arow + k0 + 4);
            qa0 = *(const float4*)(wa + k0);
            qa1 = *(const float4*)(wa + k0 + 4);
            qb0 = *(const float4*)(wb + k0);
            qb1 = *(const float4*)(wb + k0 + 4);
        }
#pragma unroll 8
        for (int kk = 0; kk < 32; ++kk)
            mk_f32(As + kk * AS_LD + w * 8, Bs + kk * 128 + lane, acc);
    }
    float bxa[4], bxb[4];
#pragma unroll
    for (int j = 0; j < 4; ++j) {
        int c = c0 + lane + 64 * j;
        bxa[j] = (b1 ? b1[c] : 0.f) + (b2 ? b2[c] : 0.f);
        bxb[j] = (b1 ? b1[c + 32] : 0.f) + (b2 ? b2[c + 32] : 0.f);
    }
#pragma unroll
    for (int i = 0; i < 8; ++i) {
        float* cr = C + (size_t)(r0 + w * 8 + i) * ldc + c0;
#pragma unroll
        for (int j = 0; j < 4; ++j) {
            float2 v = up2(acc[i * 4 + j]);
            float x = v.x + bxa[j], y = v.y + bxb[j];
            if (relu) { x = fmaxf(x, 0.f); y = fmaxf(y, 0.f); }
            cr[lane + 64 * j] = x;
            cr[lane + 64 * j + 32] = y;
        }
    }
}

// ---------------- k_scan: LSTM recurrence (unchanged, verified) ----------------
#define SCAN_SMEM ((32 + 8) * 516 * 4)
__global__ __launch_bounds__(256) void k_scan(const float* __restrict__ whh) {
    float* wsm = (float*)dynsm;
    float* hs = (float*)dynsm + 32 * 516;
    int tid = threadIdx.x, cta = blockIdx.x;
    int mbase = cta * 8;
    {
        int rowid = tid >> 3, seg = tid & 7;
        int g = rowid & 3, ml = rowid >> 2;
        const float* src = whh + (size_t)(g * 512 + mbase + ml) * 512 + seg * 64;
        float* dst = wsm + rowid * 516 + seg * 64;
#pragma unroll
        for (int q = 0; q < 64; q += 4) *(float4*)(dst + q) = *(const float4*)(src + q);
    }
    int gt = cta * 256 + tid;
    if (gt < 8192) g_hbuf[gt] = 0.f;

    int b = tid & 7, gate = (tid >> 3) & 3, ml = tid >> 5;
    int m = mbase + ml;
    float cst = 0.f;
    unsigned epoch = 1;
    gbar_ep(epoch * 64);

    int cur = 0;
    for (int t = 0; t < T_STEPS; ++t) {
        float gihv0 = 0.f, gihv1 = 0.f, gihv2 = 0.f, gihv3 = 0.f;
        if (gate == 0) {
            const float* gp = g_gih + ((size_t)t * 8 + b) * 2048 + m;
            gihv0 = __ldg(gp); gihv1 = __ldg(gp + 512);
            gihv2 = __ldg(gp + 1024); gihv3 = __ldg(gp + 1536);
        }
        {
            int bb = tid >> 5, k0 = (tid & 31) * 16;
            const float4* src = (const float4*)(g_hbuf + cur * 4096 + bb * 512 + k0);
            float* dst = hs + bb * 516 + k0;
#pragma unroll
            for (int q = 0; q < 4; ++q) *(float4*)(dst + q * 4) = __ldcg(src + q);
        }
        __syncthreads();
        u64 acc = 0ull;
        const float* wr = wsm + (ml * 4 + gate) * 516;
        const float* hr = hs + b * 516;
#pragma unroll 8
        for (int k = 0; k < 512; k += 8) {
            ulonglong2 wa = *(const ulonglong2*)(wr + k);
            ulonglong2 wb = *(const ulonglong2*)(wr + k + 4);
            ulonglong2 ha = *(const ulonglong2*)(hr + k);
            ulonglong2 hb = *(const ulonglong2*)(hr + k + 4);
            fma2(acc, wa.x, ha.x); fma2(acc, wa.y, ha.y);
            fma2(acc, wb.x, hb.x); fma2(acc, wb.y, hb.y);
        }
        float2 dv = up2(acc);
        float dot = dv.x + dv.y;
        int lb = tid & 7;
        float d0 = __shfl_sync(0xffffffffu, dot, lb + 0);
        float d1 = __shfl_sync(0xffffffffu, dot, lb + 8);
        float d2 = __shfl_sync(0xffffffffu, dot, lb + 16);
        float d3 = __shfl_sync(0xffffffffu, dot, lb + 24);
        if (gate == 0) {
            float gi = gihv0 + d0, gf = gihv1 + d1, gg = gihv2 + d2, go = gihv3 + d3;
            float cn = sigm(gf) * cst + sigm(gi) * tanhf(gg);
            float hn = sigm(go) * tanhf(cn);
            cst = cn;
            __stcg(&g_hbuf[(cur ^ 1) * 4096 + b * 512 + m], hn);
            g_hall[((size_t)t * 8 + b) * 512 + m] = hn;
        }
        cur ^= 1;
        epoch++;
        gbar_ep(epoch * 64);
    }
}

// ---------------- k_big: bf16 m16n8k16 obs-net + emission, one CTA per (t, batch) ----------------
// 512 thr = 16 warps (4x4 warp grid). Warp tile: 32 rows x 64 cols (s1) / 32 x 48 (s2).
// Packed-u32 layouts: stride ≡ 8 mod 32 -> conflict-free fragment loads (banks 8*tig+gid).
#define LDA2 136     // u32 stride, A/a2 packed [kpair][row]
#define LDB1b 264    // u32 stride, stage-1 B [kpair][col 256]
#define LDB2b 200    // u32 stride, stage-2 B [kpair][col 192]
#define A2_BYTES (128 * LDA2 * 4)     // 69632
#define ASB_BYTES (16 * LDA2 * 4)     // 8704
#define BSB_BYTES (16 * LDB1b * 4)    // 16896
#define BIG_SMEM (A2_BYTES + ASB_BYTES + BSB_BYTES)   // 95232
__global__ __launch_bounds__(512) void k_big(
    const float* __restrict__ mels, const float* __restrict__ ob1,
    const float* __restrict__ ob2, const int* __restrict__ inputs_len) {
    unsigned* a2p2 = (unsigned*)dynsm;                       // [128 kp][LDA2] packed a2
    unsigned* As2 = (unsigned*)(dynsm + A2_BYTES);           // [16 kp][LDA2] a1 chunk
    unsigned* Bs2 = (unsigned*)(dynsm + A2_BYTES + ASB_BYTES); // [16 kp][LDB1b/LDB2b]
    __shared__ float xs[80];
    __shared__ int ilen_s;
    int tid = threadIdx.x, w = tid >> 5, lane = tid & 31;
    int gid = lane >> 2, tig = lane & 3;
    int bid = blockIdx.x;
    int b = bid & 7, t = bid >> 3;
    int r0 = b * 128;
    int mrow = (w >> 2) * 32;
    int nc1 = (w & 3) * 64;
    int nc2 = (w & 3) * 48;

    if (tid < 80) xs[tid] = mels[((size_t)b * 80 + tid) * 256 + t];
    if (tid == 80) ilen_s = inputs_len[b];

    int ar = tid & 127, kq = (tid >> 7) * 8;
    const float* bp_ = g_base + (size_t)(r0 + ar) * 256 + kq;
    const float* hp_ = g_hpart + ((size_t)t * 8 + b) * 256 + kq;

    // ---- stage 1: a2 = relu(a1 @ ow1^T + ob1), 256 cols ----
    float d1[64];
#pragma unroll
    for (int i = 0; i < 64; ++i) d1[i] = 0.f;
    for (int ch = 0; ch < 8; ++ch) {
        int k0 = ch * 32;
        if (ch) __syncthreads();
        {   // fill A chunk: a1 = relu(base + hpart), bf16x2-packed [kp][row]
            float4 v0 = *(const float4*)(bp_ + k0);
            float4 v1 = *(const float4*)(bp_ + k0 + 4);
            float4 h0 = *(const float4*)(hp_ + k0);
            float4 h1 = *(const float4*)(hp_ + k0 + 4);
            unsigned* ap = As2 + (kq >> 1) * LDA2 + ar;
            ap[0 * LDA2] = pkbf(fmaxf(v0.x + h0.x, 0.f), fmaxf(v0.y + h0.y, 0.f));
            ap[1 * LDA2] = pkbf(fmaxf(v0.z + h0.z, 0.f), fmaxf(v0.w + h0.w, 0.f));
            ap[2 * LDA2] = pkbf(fmaxf(v1.x + h1.x, 0.f), fmaxf(v1.y + h1.y, 0.f));
            ap[3 * LDA2] = pkbf(fmaxf(v1.z + h1.z, 0.f), fmaxf(v1.w + h1.w, 0.f));
        }
        {   // fill B chunk: 16 kp x 256 cols = 4096 u32
#pragma unroll
            for (int e = tid; e < 4096; e += 512) {
                int kp = e >> 8, c = e & 255;
                Bs2[kp * LDB1b + c] = g_ow1b[(size_t)(ch * 16 + kp) * 256 + c];
            }
        }
        __syncthreads();
#pragma unroll
        for (int s = 0; s < 2; ++s) {
            int kA = (s * 8 + tig) * LDA2, kA4 = (s * 8 + tig + 4) * LDA2;
            unsigned a0[4], a1f[4];
            a0[0] = As2[kA + mrow + gid];       a0[1] = As2[kA + mrow + gid + 8];
            a0[2] = As2[kA4 + mrow + gid];      a0[3] = As2[kA4 + mrow + gid + 8];
            a1f[0] = As2[kA + mrow + 16 + gid]; a1f[1] = As2[kA + mrow + 16 + gid + 8];
            a1f[2] = As2[kA4 + mrow + 16 + gid]; a1f[3] = As2[kA4 + mrow + 16 + gid + 8];
            int kB = (s * 8 + tig) * LDB1b, kB4 = (s * 8 + tig + 4) * LDB1b;
#pragma unroll
            for (int nt = 0; nt < 8; ++nt) {
                unsigned b0 = Bs2[kB + nc1 + nt * 8 + gid];
                unsigned b1 = Bs2[kB4 + nc1 + nt * 8 + gid];
                mma_bf16(d1 + nt * 4, a0, b0, b1);
                mma_bf16(d1 + 32 + nt * 4, a1f, b0, b1);
            }
        }
    }
    __syncthreads();
    {   // write a2 bf16x2-packed transposed [col-pair][row] with bias+relu
#pragma unroll
        for (int mt = 0; mt < 2; ++mt) {
            int rw = mrow + mt * 16 + gid;
#pragma unroll
            for (int nt = 0; nt < 8; ++nt) {
                int cA = nc1 + nt * 8 + 2 * tig;
                int cp = cA >> 1;
                float bA = __ldg(ob1 + cA), bB = __ldg(ob1 + cA + 1);
                const float* dd = d1 + mt * 32 + nt * 4;
                a2p2[cp * LDA2 + rw] = pkbf(fmaxf(dd[0] + bA, 0.f), fmaxf(dd[1] + bB, 0.f));
                a2p2[cp * LDA2 + rw + 8] = pkbf(fmaxf(dd[2] + bA, 0.f), fmaxf(dd[3] + bB, 0.f));
            }
        }
    }
    __syncthreads();
    // ---- stage 2: p = a2 @ ow2^T + ob2 (161 cols via 192) ----
    float d2[48];
#pragma unroll
    for (int i = 0; i < 48; ++i) d2[i] = 0.f;
    for (int ch = 0; ch < 8; ++ch) {
        if (ch) __syncthreads();
        {   // fill B chunk: 16 kp x 192 = 3072 u32
#pragma unroll
            for (int e = tid; e < 3072; e += 512) {
                int kp = e / 192, c = e - kp * 192;
                Bs2[kp * LDB2b + c] = g_ow2b[(size_t)(ch * 16 + kp) * 192 + c];
            }
        }
        __syncthreads();
#pragma unroll
        for (int s = 0; s < 2; ++s) {
            int kA = (ch * 16 + s * 8 + tig) * LDA2, kA4 = kA + 4 * LDA2;
            unsigned a0[4], a1f[4];
            a0[0] = a2p2[kA + mrow + gid];       a0[1] = a2p2[kA + mrow + gid + 8];
            a0[2] = a2p2[kA4 + mrow + gid];      a0[3] = a2p2[kA4 + mrow + gid + 8];
            a1f[0] = a2p2[kA + mrow + 16 + gid]; a1f[1] = a2p2[kA + mrow + 16 + gid + 8];
            a1f[2] = a2p2[kA4 + mrow + 16 + gid]; a1f[3] = a2p2[kA4 + mrow + 16 + gid + 8];
            int kB = (s * 8 + tig) * LDB2b, kB4 = (s * 8 + tig + 4) * LDB2b;
#pragma unroll
            for (int nt = 0; nt < 6; ++nt) {
                unsigned b0 = Bs2[kB + nc2 + nt * 8 + gid];
                unsigned b1 = Bs2[kB4 + nc2 + nt * 8 + gid];
                mma_bf16(d2 + nt * 4, a0, b0, b1);
                mma_bf16(d2 + 24 + nt * 4, a1f, b0, b1);
            }
        }
    }
    __syncthreads();
    float* ps = (float*)dynsm;   // overlay [128][164] f32
    {
#pragma unroll
        for (int mt = 0; mt < 2; ++mt) {
            int rw = mrow + mt * 16 + gid;
#pragma unroll
            for (int nt = 0; nt < 6; ++nt) {
                int cA = nc2 + nt * 8 + 2 * tig, cB = cA + 1;
                const float* dd = d2 + mt * 24 + nt * 4;
                if (cA < 161) {
                    float bb = __ldg(ob2 + cA);
                    ps[rw * 164 + cA] = dd[0] + bb;
                    ps[(rw + 8) * 164 + cA] = dd[2] + bb;
                }
                if (cB < 161) {
                    float bb = __ldg(ob2 + cB);
                    ps[rw * 164 + cB] = dd[1] + bb;
                    ps[(rw + 8) * 164 + cB] = dd[3] + bb;
                }
            }
        }
    }
    __syncthreads();
    {   // emission: warp w -> rows w*8..+8; 4 lanes per row, 20 d's each
        int ri = lane >> 2, part = lane & 3;
        int row = w * 8 + ri;
        const float* pr = ps + row * 164;
        float sum = 0.f;
        int d0 = part * 20;
        for (int d = d0; d < d0 + 20; ++d) {
            float mean = pr[d], sh = pr[80 + d];
            float stdv = fmaxf(sh, 0.f) + log1pf(expf(-fabsf(sh))) + 1e-3f;
            float z = (xs[d] - mean) / stdv;
            sum += -0.5f * z * z - logf(stdv) - HALF_LOG2PI;
        }
        sum += __shfl_xor_sync(0xffffffffu, sum, 1);
        sum += __shfl_xor_sync(0xffffffffu, sum, 2);
        if (part == 0) {
            int n = row;
            g_em[((size_t)t * 8 + b) * 128 + n] = (n < ilen_s) ? sum : 0.f;
            g_tv[((size_t)t * 8 + b) * 128 + n] = pr[160];
        }
    }
}

// ---------------- k_hmm: one warp per batch, shuffle-only ----------------
__global__ __launch_bounds__(32) void k_hmm(
    const int* __restrict__ inputs_len, const int* __restrict__ mel_lens,
    float* __restrict__ out) {
    int b = blockIdx.x, lane = threadIdx.x;
    int ilen = inputs_len[b], mlen = mel_lens[b];
    float la[4];
    float lp = 0.f;
    float* outla = out + 8 + (size_t)b * 256 * 128;
    float emc[4], tvc[4];
#pragma unroll
    for (int q = 0; q < 4; ++q) {
        emc[q] = g_em[(size_t)b * 128 + q * 32 + lane];
        tvc[q] = g_tv[(size_t)b * 128 + q * 32 + lane];
    }
    for (int t = 0; t < T_STEPS; ++t) {
        float emn[4], tvn[4];
        if (t + 1 < T_STEPS) {
#pragma unroll
            for (int q = 0; q < 4; ++q) {
                emn[q] = __ldcg(&g_em[((size_t)(t + 1) * 8 + b) * 128 + q * 32 + lane]);
                tvn[q] = __ldcg(&g_tv[((size_t)(t + 1) * 8 + b) * 128 + q * 32 + lane]);
            }
        }
        float la_t[4];
        if (t == 0) {
#pragma unroll
            for (int q = 0; q < 4; ++q)
                la_t[q] = emc[q] + ((q == 0 && lane == 0) ? 0.f : NEG);
        } else {
            float st_[4], mvv[4];
#pragma unroll
            for (int q = 0; q < 4; ++q) {
                float tv = tvc[q];
                float lstay = logf(fmaxf(1.f / (1.f + expf(tv)), 1e-4f));
                float lmove = logf(fmaxf(1.f / (1.f + expf(-tv)), 1e-4f));
                st_[q] = la[q] + lstay;
                mvv[q] = la[q] + lmove;
            }
            float lv[4];
#pragma unroll
            for (int q = 0; q < 4; ++q)
                lv[q] = __shfl_up_sync(0xffffffffu, mvv[q], 1);
            float c1 = __shfl_sync(0xffffffffu, mvv[0], 31);
            float c2 = __shfl_sync(0xffffffffu, mvv[1], 31);
            float c3 = __shfl_sync(0xffffffffu, mvv[2], 31);
            if (lane == 0) { lv[0] = NEG; lv[1] = c1; lv[2] = c2; lv[3] = c3; }
#pragma unroll
            for (int q = 0; q < 4; ++q) {
                float mx = fmaxf(st_[q], lv[q]);
                float mn = fminf(st_[q], lv[q]);
                float o = mx + log1pf(expf(mn - mx));
                int n = q * 32 + lane;
                o = (n < ilen) ? o : NEG;
                la_t[q] = emc[q] + o;
            }
        }
        float mx = fmaxf(fmaxf(la_t[0], la_t[1]), fmaxf(la_t[2], la_t[3]));
#pragma unroll
        for (int off = 16; off; off >>= 1)
            mx = fmaxf(mx, __shfl_xor_sync(0xffffffffu, mx, off));
        float s = expf(la_t[0] - mx) + expf(la_t[1] - mx) +
                  expf(la_t[2] - mx) + expf(la_t[3] - mx);
#pragma unroll
        for (int off = 16; off; off >>= 1)
            s += __shfl_xor_sync(0xffffffffu, s, off);
        float log_c = mx + logf(s);
#pragma unroll
        for (int q = 0; q < 4; ++q) {
            la[q] = la_t[q] - log_c;
            outla[(size_t)t * 128 + q * 32 + lane] = la[q];
        }
        if (t < mlen) lp += log_c;
#pragma unroll
        for (int q = 0; q < 4; ++q) { emc[q] = emn[q]; tvc[q] = tvn[q]; }
    }
    if (lane == 0) out[b] = lp;
}

// ---------------- launch ----------------
#define GEMM_SMEM (AS_BYTES + 32768)

extern "C" void kernel_launch(void* const* d_in, const int* in_sizes, int n_in,
                              void* d_out, int out_size) {
    const float* inputs = (const float*)d_in[0];
    const float* mels = (const float*)d_in[1];
    const float* pw0 = (const float*)d_in[2];
    const float* pw1 = (const float*)d_in[3];
    const float* wih = (const float*)d_in[4];
    const float* whh = (const float*)d_in[5];
    const float* bih = (const float*)d_in[6];
    const float* bhh = (const float*)d_in[7];
    const float* ow0 = (const float*)d_in[8];
    const float* ob0 = (const float*)d_in[9];
    const float* ow1 = (const float*)d_in[10];
    const float* ob1 = (const float*)d_in[11];
    const float* ow2 = (const float*)d_in[12];
    const float* ob2 = (const float*)d_in[13];
    const int* inputs_len = (const int*)d_in[14];
    const int* mel_lens = (const int*)d_in[15];
    float* out = (float*)d_out;

    cudaFuncSetAttribute(k_scan, cudaFuncAttributeMaxDynamicSharedMemorySize, SCAN_SMEM);
    cudaFuncSetAttribute(k_big, cudaFuncAttributeMaxDynamicSharedMemorySize, BIG_SMEM);
    cudaFuncSetAttribute(k_gemm, cudaFuncAttributeMaxDynamicSharedMemorySize, GEMM_SMEM);

    float *arwin, *w0p, *pre, *base, *hall, *hpart, *gih;
    cudaGetSymbolAddress((void**)&arwin, g_arwin);
    cudaGetSymbolAddress((void**)&w0p, g_w0p);
    cudaGetSymbolAddress((void**)&pre, g_pre);
    cudaGetSymbolAddress((void**)&base, g_base);
    cudaGetSymbolAddress((void**)&hall, g_hall);
    cudaGetSymbolAddress((void**)&hpart, g_hpart);
    cudaGetSymbolAddress((void**)&gih, g_gih);

    k_prep<<<256, 256>>>(mels, pw0, ow1, ow2);
    // p0 = relu(arwin @ w0p^T) -> g_hpart (scratch)
    k_gemm<<<dim3(16, 1), 512, GEMM_SMEM>>>(arwin, 96, 96, w0p, 96, 255, nullptr, nullptr, hpart, 256, 1);
    // pre1 = relu(p0 @ pw1^T) -> g_pre
    k_gemm<<<dim3(16, 1), 512, GEMM_SMEM>>>(hpart, 256, 256, pw1, 256, 255, nullptr, nullptr, pre, 256, 1);
    // gih = pre1 @ wih^T + bih + bhh
    k_gemm<<<dim3(16, 8), 512, GEMM_SMEM>>>(pre, 256, 256, wih, 256, 2047, bih, bhh, gih, 2048, 0);
    // base = inputs @ ow0[:, :512]^T + ob0
    k_gemm<<<dim3(8, 1), 512, GEMM_SMEM>>>(inputs, 512, 512, ow0, 1024, 255, ob0, nullptr, base, 256, 0);
    // LSTM scan
    k_scan<<<64, 256, SCAN_SMEM>>>(whh);
    // hpart = hall @ ow0[:, 512:]^T
    k_gemm<<<dim3(16, 1), 512, GEMM_SMEM>>>(hall, 512, 512, ow0 + 512, 1024, 255, nullptr, nullptr, hpart, 256, 0);
    // fused obs-net + emission (bf16 m16n8k16 tensor cores): one CTA per (t, batch)
    k_big<<<2048, 512, BIG_SMEM>>>(mels, ob1, ob2, inputs_len);
    // HMM forward
    k_hmm<<<8, 32>>>(inputs_len, mel_lens, out);
}

// round 15
// speedup vs baseline: 1.8375x; 1.1603x over previous
#include <cuda_runtime.h>
#include <cuda_fp16.h>
#include <cstdint>

#define T_STEPS 256
#define NEG (-1.0e10f)
#define HALF_LOG2PI 0.9189385332046727f
typedef unsigned long long u64;

extern __shared__ char dynsm[];   // single dynamic-smem symbol

// ---------------- global scratch ----------------
__device__ float g_arwin[2048 * 96];
__device__ float g_w0p[256 * 96];
__device__ float g_pre[2048 * 256];
__device__ float g_gih[2048 * 2048];    // PERMUTED cols: j = m*4 + g
__device__ float g_base[1024 * 256];
__device__ float g_hall[2048 * 512];
__device__ float g_hpart[2048 * 256];   // also p0 scratch
__device__ float g_em[2048 * 128];
__device__ float g_tv[2048 * 128];
__device__ unsigned g_ow1b[128 * 256];  // ow1 bf16x2-packed [kpair][col]
__device__ unsigned g_ow2b[128 * 192];  // ow2 bf16x2-packed [kpair][col<192], 0-padded
__device__ float g_wihp[2048 * 256];    // wih rows permuted j = m*4+g
__device__ float g_bp[2048];            // permuted bih+bhh
__device__ unsigned g_whhh[256 * 32 * 32 * 2];  // whh fp16x2 B-fragments [ntile][chunk][lane][2]
__device__ unsigned g_hbh[2 * 2048];    // h hi fp16x2, [parity][b*256+kp]
__device__ unsigned g_hbl[2 * 2048];    // h lo fp16x2
__device__ unsigned g_cnt;
__device__ unsigned g_gen;

// ---------------- helpers ----------------
__device__ __forceinline__ u64 pk2(float x) {
    u64 r; asm("mov.b64 %0, {%1, %1};" : "=l"(r) : "f"(x)); return r;
}
__device__ __forceinline__ u64 pkxy(float x, float y) {
    u64 r; asm("mov.b64 %0, {%1, %2};" : "=l"(r) : "f"(x), "f"(y)); return r;
}
__device__ __forceinline__ void fma2(u64& d, u64 a, u64 b) {
    asm("fma.rn.f32x2 %0, %1, %2, %0;" : "+l"(d) : "l"(a), "l"(b));
}
__device__ __forceinline__ float2 up2(u64 v) {
    float2 f; asm("mov.b64 {%0, %1}, %2;" : "=f"(f.x), "=f"(f.y) : "l"(v)); return f;
}
__device__ __forceinline__ float sigm(float x) { return 1.f / (1.f + expf(-x)); }
__device__ __forceinline__ unsigned pkbf(float lo, float hi) {
    unsigned r; asm("cvt.rn.bf16x2.f32 %0, %1, %2;" : "=r"(r) : "f"(hi), "f"(lo));
    return r;
}
__device__ __forceinline__ unsigned pkhf(float lo, float hi) {
    unsigned r; asm("cvt.rn.f16x2.f32 %0, %1, %2;" : "=r"(r) : "f"(hi), "f"(lo));
    return r;
}
__device__ __forceinline__ void mma_bf16(float* d, const unsigned* a,
                                         unsigned b0, unsigned b1) {
    asm("mma.sync.aligned.m16n8k16.row.col.f32.bf16.bf16.f32 "
        "{%0,%1,%2,%3}, {%4,%5,%6,%7}, {%8,%9}, {%0,%1,%2,%3};"
        : "+f"(d[0]), "+f"(d[1]), "+f"(d[2]), "+f"(d[3])
        : "r"(a[0]), "r"(a[1]), "r"(a[2]), "r"(a[3]), "r"(b0), "r"(b1));
}
__device__ __forceinline__ void mma_f16(float* d, unsigned a0, unsigned a2,
                                        unsigned b0, unsigned b1) {
    asm("mma.sync.aligned.m16n8k16.row.col.f32.f16.f16.f32 "
        "{%0,%1,%2,%3}, {%4,%5,%6,%7}, {%8,%9}, {%0,%1,%2,%3};"
        : "+f"(d[0]), "+f"(d[1]), "+f"(d[2]), "+f"(d[3])
        : "r"(a0), "r"(0u), "r"(a2), "r"(0u), "r"(b0), "r"(b1));
}

// epoch grid barrier: monotonic counter, release/acquire
__device__ __forceinline__ void gbar_ep(unsigned target) {
    __syncthreads();
    if (threadIdx.x == 0) {
        unsigned old;
        asm volatile("atom.release.gpu.global.add.u32 %0, [%1], %2;"
                     : "=r"(old) : "l"(&g_cnt), "r"(1u) : "memory");
        if (old + 1u == target) {
            asm volatile("st.release.gpu.global.u32 [%0], %1;"
                         :: "l"(&g_gen), "r"(target) : "memory");
        } else {
            unsigned cur;
            do {
                asm volatile("ld.acquire.gpu.global.u32 %0, [%1];"
                             : "=r"(cur) : "l"(&g_gen) : "memory");
            } while (cur < target);
        }
    }
    __syncthreads();
}

#define AS_LD 132   // f32 stride for k_gemm transposed A tile [32][AS_LD]
#define AS_BYTES (32 * AS_LD * 4)   // 16896

// inner micro step for k_gemm: 8 rows x 4 u64-cols
__device__ __forceinline__ void mk_f32(const float* __restrict__ Ak,
                                       const u64* __restrict__ br, u64* acc) {
    float4 a0 = *(const float4*)(Ak);
    float4 a1 = *(const float4*)(Ak + 4);
    u64 b0 = br[0], b1 = br[32], b2 = br[64], b3 = br[96];
    u64 p;
    p = pk2(a0.x); fma2(acc[0], p, b0); fma2(acc[1], p, b1); fma2(acc[2], p, b2); fma2(acc[3], p, b3);
    p = pk2(a0.y); fma2(acc[4], p, b0); fma2(acc[5], p, b1); fma2(acc[6], p, b2); fma2(acc[7], p, b3);
    p = pk2(a0.z); fma2(acc[8], p, b0); fma2(acc[9], p, b1); fma2(acc[10], p, b2); fma2(acc[11], p, b3);
    p = pk2(a0.w); fma2(acc[12], p, b0); fma2(acc[13], p, b1); fma2(acc[14], p, b2); fma2(acc[15], p, b3);
    p = pk2(a1.x); fma2(acc[16], p, b0); fma2(acc[17], p, b1); fma2(acc[18], p, b2); fma2(acc[19], p, b3);
    p = pk2(a1.y); fma2(acc[20], p, b0); fma2(acc[21], p, b1); fma2(acc[22], p, b2); fma2(acc[23], p, b3);
    p = pk2(a1.z); fma2(acc[24], p, b0); fma2(acc[25], p, b1); fma2(acc[26], p, b2); fma2(acc[27], p, b3);
    p = pk2(a1.w); fma2(acc[28], p, b0); fma2(acc[29], p, b1); fma2(acc[30], p, b2); fma2(acc[31], p, b3);
}

// ---------------- k_prep ----------------
__global__ __launch_bounds__(256) void k_prep(const float* __restrict__ mels,
                                              const float* __restrict__ w0,
                                              const float* __restrict__ ow1,
                                              const float* __restrict__ ow2,
                                              const float* __restrict__ wih,
                                              const float* __restrict__ whh,
                                              const float* __restrict__ bih,
                                              const float* __restrict__ bhh) {
    int i0 = blockIdx.x * 256 + threadIdx.x;
    int stride = gridDim.x * 256;
    if (i0 == 0) { g_cnt = 0; g_gen = 0; }
    for (int e = i0; e < 2048 * 96; e += stride) {
        int r = e / 96, k = e - r * 96;
        int t = r >> 3, b = r & 7;
        g_arwin[e] = (k < 80 && t > 0) ? mels[((size_t)b * 80 + k) * 256 + t - 1] : 0.f;
    }
    for (int e = i0; e < 256 * 96; e += stride) {
        int c = e / 96, k = e - c * 96;
        g_w0p[e] = (k < 80) ? w0[c * 80 + k] : 0.f;
    }
    for (int e = i0; e < 32768; e += stride) {   // ow1 bf16-pack [kp][col]
        int kp = e >> 8, c = e & 255;
        g_ow1b[e] = pkbf(ow1[c * 256 + 2 * kp], ow1[c * 256 + 2 * kp + 1]);
    }
    for (int e = i0; e < 24576; e += stride) {   // ow2 bf16-pack [kp][col], padded
        int kp = e / 192, c = e - kp * 192;
        g_ow2b[e] = (c < 161) ? pkbf(ow2[c * 256 + 2 * kp], ow2[c * 256 + 2 * kp + 1]) : 0u;
    }
    // permuted wih rows: j = m*4+g -> wih row g*512 + m
    for (int e = i0; e < 2048 * 256; e += stride) {
        int j = e >> 8, k = e & 255;
        int m = j >> 2, g = j & 3;
        g_wihp[e] = wih[((size_t)(g * 512 + m)) * 256 + k];
    }
    for (int e = i0; e < 2048; e += stride) {
        int m = e >> 2, g = e & 3;
        g_bp[e] = bih[g * 512 + m] + bhh[g * 512 + m];
    }
    // whh fp16 B-fragments: [ntile][chunk][lane][2]
    for (int e = i0; e < 524288; e += stride) {
        int r = e & 1;
        int lane = (e >> 1) & 31;
        int c = (e >> 6) & 31;
        int nt = e >> 11;
        int j = nt * 8 + (lane >> 2);         // permuted col
        int m = j >> 2, g = j & 3;
        int k = c * 16 + 2 * (lane & 3) + (r ? 8 : 0);
        const float* row = whh + (size_t)(g * 512 + m) * 512;
        g_whhh[e] = pkhf(row[k], row[k + 1]);
    }
    for (int e = i0; e < 2 * 2048; e += stride) { g_hbh[e] = 0u; g_hbl[e] = 0u; }
}

// ---------------- generic GEMM: 128x256 tile, 512 thr, fp32 f32x2, prefetched ----------------
__global__ __launch_bounds__(512) void k_gemm(
    const float* __restrict__ A, int lda, int K,
    const float* __restrict__ W, int ldw, int wmax,
    const float* __restrict__ b1, const float* __restrict__ b2,
    float* __restrict__ C, int ldc, int relu) {
    float* As = (float*)dynsm;
    u64* Bs = (u64*)(dynsm + AS_BYTES);
    int tid = threadIdx.x, w = tid >> 5, lane = tid & 31;
    int r0 = blockIdx.x * 128, c0 = blockIdx.y * 256;
    u64 acc[32];
#pragma unroll
    for (int i = 0; i < 32; ++i) acc[i] = 0ull;
    int ar = tid & 127, kq = (tid >> 7) * 8;
    const float* Arow = A + (size_t)(r0 + ar) * lda + kq;
    int bp = tid & 127;
    int ca = c0 + (bp & 31) + 64 * (bp >> 5);
    int cb = ca + 32;
    if (ca > wmax) ca = wmax;
    if (cb > wmax) cb = wmax;
    const float* wa = W + (size_t)ca * ldw + kq;
    const float* wb = W + (size_t)cb * ldw + kq;
    int nch = K >> 5;

    float4 pa0 = *(const float4*)(Arow);
    float4 pa1 = *(const float4*)(Arow + 4);
    float4 qa0 = *(const float4*)(wa);
    float4 qa1 = *(const float4*)(wa + 4);
    float4 qb0 = *(const float4*)(wb);
    float4 qb1 = *(const float4*)(wb + 4);

    for (int ch = 0; ch < nch; ++ch) {
        if (ch) __syncthreads();
        {
            float* ap = As + kq * AS_LD + ar;
            ap[0 * AS_LD] = pa0.x; ap[1 * AS_LD] = pa0.y;
            ap[2 * AS_LD] = pa0.z; ap[3 * AS_LD] = pa0.w;
            ap[4 * AS_LD] = pa1.x; ap[5 * AS_LD] = pa1.y;
            ap[6 * AS_LD] = pa1.z; ap[7 * AS_LD] = pa1.w;
        }
        {
            u64* dst = Bs + kq * 128 + bp;
            dst[0 * 128] = pkxy(qa0.x, qb0.x); dst[1 * 128] = pkxy(qa0.y, qb0.y);
            dst[2 * 128] = pkxy(qa0.z, qb0.z); dst[3 * 128] = pkxy(qa0.w, qb0.w);
            dst[4 * 128] = pkxy(qa1.x, qb1.x); dst[5 * 128] = pkxy(qa1.y, qb1.y);
            dst[6 * 128] = pkxy(qa1.z, qb1.z); dst[7 * 128] = pkxy(qa1.w, qb1.w);
        }
        __syncthreads();
        if (ch + 1 < nch) {
            int k0 = (ch + 1) * 32;
            pa0 = *(const float4*)(Arow + k0);
            pa1 = *(const float4*)(Arow + k0 + 4);
            qa0 = *(const float4*)(wa + k0);
            qa1 = *(const float4*)(wa + k0 + 4);
            qb0 = *(const float4*)(wb + k0);
            qb1 = *(const float4*)(wb + k0 + 4);
        }
#pragma unroll 8
        for (int kk = 0; kk < 32; ++kk)
            mk_f32(As + kk * AS_LD + w * 8, Bs + kk * 128 + lane, acc);
    }
    float bxa[4], bxb[4];
#pragma unroll
    for (int j = 0; j < 4; ++j) {
        int c = c0 + lane + 64 * j;
        bxa[j] = (b1 ? b1[c] : 0.f) + (b2 ? b2[c] : 0.f);
        bxb[j] = (b1 ? b1[c + 32] : 0.f) + (b2 ? b2[c + 32] : 0.f);
    }
#pragma unroll
    for (int i = 0; i < 8; ++i) {
        float* cr = C + (size_t)(r0 + w * 8 + i) * ldc + c0;
#pragma unroll
        for (int j = 0; j < 4; ++j) {
            float2 v = up2(acc[i * 4 + j]);
            float x = v.x + bxa[j], y = v.y + bxb[j];
            if (relu) { x = fmaxf(x, 0.f); y = fmaxf(y, 0.f); }
            cr[lane + 64 * j] = x;
            cr[lane + 64 * j + 32] = y;
        }
    }
}

// ---------------- k_scan: fp16 MMA LSTM recurrence, weights in registers ----------------
// 32 CTAs x 256 thr (8 warps). CTA owns 64 permuted cols (16 units); warp owns one n8 tile.
__global__ __launch_bounds__(256) void k_scan() {
    __shared__ unsigned hs_hi[8 * 260];
    __shared__ unsigned hs_lo[8 * 260];
    int tid = threadIdx.x, w = tid >> 5, lane = tid & 31;
    int cta = blockIdx.x;
    int nt = cta * 8 + w;
    int b4 = lane >> 2, tig = lane & 3;

    // load B fragments (whh slice) into registers - once
    unsigned breg[64];
    {
        const unsigned* bpr = g_whhh + (size_t)nt * 2048 + lane * 2;
#pragma unroll
        for (int c = 0; c < 32; ++c) {
            breg[2 * c] = bpr[c * 64];
            breg[2 * c + 1] = bpr[c * 64 + 1];
        }
    }
    int us = tig >> 1;                      // unit-select within warp tile
    int mg = cta * 16 + w * 2 + us;         // global unit (combiner lanes)
    int abase = b4 * 260 + tig;
    float cst = 0.f;
    unsigned epoch = 0;                     // FIX: first barrier target = 32 (1 call x 32 CTAs)

    for (int t = 0; t < T_STEPS; ++t) {
        int par = t & 1;
        // load h (hi+lo fp16x2) into smem
        for (int e = tid; e < 2048; e += 256) {
            int bb = e >> 8, kp = e & 255;
            hs_hi[bb * 260 + kp] = __ldcg(&g_hbh[par * 2048 + e]);
            hs_lo[bb * 260 + kp] = __ldcg(&g_hbl[par * 2048 + e]);
        }
        // prefetch gih (permuted) for combiner
        float4 gv = make_float4(0.f, 0.f, 0.f, 0.f);
        if ((lane & 1) == 0)
            gv = *(const float4*)(g_gih + ((size_t)t * 8 + b4) * 2048 + mg * 4);
        __syncthreads();
        float d[4] = {0.f, 0.f, 0.f, 0.f};
#pragma unroll 8
        for (int c = 0; c < 32; ++c) {
            unsigned a0h = hs_hi[abase + c * 8];
            unsigned a2h = hs_hi[abase + c * 8 + 4];
            unsigned a0l = hs_lo[abase + c * 8];
            unsigned a2l = hs_lo[abase + c * 8 + 4];
            mma_f16(d, a0h, a2h, breg[2 * c], breg[2 * c + 1]);
            mma_f16(d, a0l, a2l, breg[2 * c], breg[2 * c + 1]);
        }
        // combine gates: lanes tig even hold (i,f); partner lane^1 holds (g,o)
        float ggv = __shfl_xor_sync(0xffffffffu, d[0], 1);
        float gov = __shfl_xor_sync(0xffffffffu, d[1], 1);
        if ((lane & 1) == 0) {
            float gi = gv.x + d[0];
            float gf = gv.y + d[1];
            float gg = gv.z + ggv;
            float go = gv.w + gov;
            float cn = sigm(gf) * cst + sigm(gi) * tanhf(gg);
            float hn = sigm(go) * tanhf(cn);
            cst = cn;
            unsigned short hb, lb2;
            asm("cvt.rn.f16.f32 %0, %1;" : "=h"(hb) : "f"(hn));
            float hif;
            asm("cvt.f32.f16 %0, %1;" : "=f"(hif) : "h"(hb));
            float lof = hn - hif;
            asm("cvt.rn.f16.f32 %0, %1;" : "=h"(lb2) : "f"(lof));
            int p2 = par ^ 1;
            unsigned short* dh = (unsigned short*)g_hbh + p2 * 4096 + b4 * 512 + mg;
            unsigned short* dl = (unsigned short*)g_hbl + p2 * 4096 + b4 * 512 + mg;
            asm volatile("st.global.cg.b16 [%0], %1;" :: "l"(dh), "h"(hb));
            asm volatile("st.global.cg.b16 [%0], %1;" :: "l"(dl), "h"(lb2));
            g_hall[((size_t)t * 8 + b4) * 512 + mg] = hn;
        }
        epoch++;
        gbar_ep(epoch * 32);
    }
}

// ---------------- k_big: bf16 m16n8k16 obs-net + emission (unchanged, verified) ----------------
#define LDA2 136
#define LDB1b 264
#define LDB2b 200
#define A2_BYTES (128 * LDA2 * 4)
#define ASB_BYTES (16 * LDA2 * 4)
#define BSB_BYTES (16 * LDB1b * 4)
#define BIG_SMEM (A2_BYTES + ASB_BYTES + BSB_BYTES)
__global__ __launch_bounds__(512) void k_big(
    const float* __restrict__ mels, const float* __restrict__ ob1,
    const float* __restrict__ ob2, const int* __restrict__ inputs_len) {
    unsigned* a2p2 = (unsigned*)dynsm;
    unsigned* As2 = (unsigned*)(dynsm + A2_BYTES);
    unsigned* Bs2 = (unsigned*)(dynsm + A2_BYTES + ASB_BYTES);
    __shared__ float xs[80];
    __shared__ int ilen_s;
    int tid = threadIdx.x, w = tid >> 5, lane = tid & 31;
    int gid = lane >> 2, tig = lane & 3;
    int bid = blockIdx.x;
    int b = bid & 7, t = bid >> 3;
    int r0 = b * 128;
    int mrow = (w >> 2) * 32;
    int nc1 = (w & 3) * 64;
    int nc2 = (w & 3) * 48;

    if (tid < 80) xs[tid] = mels[((size_t)b * 80 + tid) * 256 + t];
    if (tid == 80) ilen_s = inputs_len[b];

    int ar = tid & 127, kq = (tid >> 7) * 8;
    const float* bp_ = g_base + (size_t)(r0 + ar) * 256 + kq;
    const float* hp_ = g_hpart + ((size_t)t * 8 + b) * 256 + kq;

    float d1[64];
#pragma unroll
    for (int i = 0; i < 64; ++i) d1[i] = 0.f;
    for (int ch = 0; ch < 8; ++ch) {
        int k0 = ch * 32;
        if (ch) __syncthreads();
        {
            float4 v0 = *(const float4*)(bp_ + k0);
            float4 v1 = *(const float4*)(bp_ + k0 + 4);
            float4 h0 = *(const float4*)(hp_ + k0);
            float4 h1 = *(const float4*)(hp_ + k0 + 4);
            unsigned* ap = As2 + (kq >> 1) * LDA2 + ar;
            ap[0 * LDA2] = pkbf(fmaxf(v0.x + h0.x, 0.f), fmaxf(v0.y + h0.y, 0.f));
            ap[1 * LDA2] = pkbf(fmaxf(v0.z + h0.z, 0.f), fmaxf(v0.w + h0.w, 0.f));
            ap[2 * LDA2] = pkbf(fmaxf(v1.x + h1.x, 0.f), fmaxf(v1.y + h1.y, 0.f));
            ap[3 * LDA2] = pkbf(fmaxf(v1.z + h1.z, 0.f), fmaxf(v1.w + h1.w, 0.f));
        }
        {
#pragma unroll
            for (int e = tid; e < 4096; e += 512) {
                int kp = e >> 8, c = e & 255;
                Bs2[kp * LDB1b + c] = g_ow1b[(size_t)(ch * 16 + kp) * 256 + c];
            }
        }
        __syncthreads();
#pragma unroll
        for (int s = 0; s < 2; ++s) {
            int kA = (s * 8 + tig) * LDA2, kA4 = (s * 8 + tig + 4) * LDA2;
            unsigned a0[4], a1f[4];
            a0[0] = As2[kA + mrow + gid];       a0[1] = As2[kA + mrow + gid + 8];
            a0[2] = As2[kA4 + mrow + gid];      a0[3] = As2[kA4 + mrow + gid + 8];
            a1f[0] = As2[kA + mrow + 16 + gid]; a1f[1] = As2[kA + mrow + 16 + gid + 8];
            a1f[2] = As2[kA4 + mrow + 16 + gid]; a1f[3] = As2[kA4 + mrow + 16 + gid + 8];
            int kB = (s * 8 + tig) * LDB1b, kB4 = (s * 8 + tig + 4) * LDB1b;
#pragma unroll
            for (int ntI = 0; ntI < 8; ++ntI) {
                unsigned b0 = Bs2[kB + nc1 + ntI * 8 + gid];
                unsigned b1 = Bs2[kB4 + nc1 + ntI * 8 + gid];
                mma_bf16(d1 + ntI * 4, a0, b0, b1);
                mma_bf16(d1 + 32 + ntI * 4, a1f, b0, b1);
            }
        }
    }
    __syncthreads();
    {
#pragma unroll
        for (int mt = 0; mt < 2; ++mt) {
            int rw = mrow + mt * 16 + gid;
#pragma unroll
            for (int ntI = 0; ntI < 8; ++ntI) {
                int cA = nc1 + ntI * 8 + 2 * tig;
                int cp = cA >> 1;
                float bA = __ldg(ob1 + cA), bB = __ldg(ob1 + cA + 1);
                const float* dd = d1 + mt * 32 + ntI * 4;
                a2p2[cp * LDA2 + rw] = pkbf(fmaxf(dd[0] + bA, 0.f), fmaxf(dd[1] + bB, 0.f));
                a2p2[cp * LDA2 + rw + 8] = pkbf(fmaxf(dd[2] + bA, 0.f), fmaxf(dd[3] + bB, 0.f));
            }
        }
    }
    __syncthreads();
    float d2[48];
#pragma unroll
    for (int i = 0; i < 48; ++i) d2[i] = 0.f;
    for (int ch = 0; ch < 8; ++ch) {
        if (ch) __syncthreads();
        {
#pragma unroll
            for (int e = tid; e < 3072; e += 512) {
                int kp = e / 192, c = e - kp * 192;
                Bs2[kp * LDB2b + c] = g_ow2b[(size_t)(ch * 16 + kp) * 192 + c];
            }
        }
        __syncthreads();
#pragma unroll
        for (int s = 0; s < 2; ++s) {
            int kA = (ch * 16 + s * 8 + tig) * LDA2, kA4 = kA + 4 * LDA2;
            unsigned a0[4], a1f[4];
            a0[0] = a2p2[kA + mrow + gid];       a0[1] = a2p2[kA + mrow + gid + 8];
            a0[2] = a2p2[kA4 + mrow + gid];      a0[3] = a2p2[kA4 + mrow + gid + 8];
            a1f[0] = a2p2[kA + mrow + 16 + gid]; a1f[1] = a2p2[kA + mrow + 16 + gid + 8];
            a1f[2] = a2p2[kA4 + mrow + 16 + gid]; a1f[3] = a2p2[kA4 + mrow + 16 + gid + 8];
            int kB = (s * 8 + tig) * LDB2b, kB4 = (s * 8 + tig + 4) * LDB2b;
#pragma unroll
            for (int ntI = 0; ntI < 6; ++ntI) {
                unsigned b0 = Bs2[kB + nc2 + ntI * 8 + gid];
                unsigned b1 = Bs2[kB4 + nc2 + ntI * 8 + gid];
                mma_bf16(d2 + ntI * 4, a0, b0, b1);
                mma_bf16(d2 + 24 + ntI * 4, a1f, b0, b1);
            }
        }
    }
    __syncthreads();
    float* ps = (float*)dynsm;
    {
#pragma unroll
        for (int mt = 0; mt < 2; ++mt) {
            int rw = mrow + mt * 16 + gid;
#pragma unroll
            for (int ntI = 0; ntI < 6; ++ntI) {
                int cA = nc2 + ntI * 8 + 2 * tig, cB = cA + 1;
                const float* dd = d2 + mt * 24 + ntI * 4;
                if (cA < 161) {
                    float bb = __ldg(ob2 + cA);
                    ps[rw * 164 + cA] = dd[0] + bb;
                    ps[(rw + 8) * 164 + cA] = dd[2] + bb;
                }
                if (cB < 161) {
                    float bb = __ldg(ob2 + cB);
                    ps[rw * 164 + cB] = dd[1] + bb;
                    ps[(rw + 8) * 164 + cB] = dd[3] + bb;
                }
            }
        }
    }
    __syncthreads();
    {
        int ri = lane >> 2, part = lane & 3;
        int row = w * 8 + ri;
        const float* pr = ps + row * 164;
        float sum = 0.f;
        int d0 = part * 20;
        for (int d = d0; d < d0 + 20; ++d) {
            float mean = pr[d], sh = pr[80 + d];
            float stdv = fmaxf(sh, 0.f) + log1pf(expf(-fabsf(sh))) + 1e-3f;
            float z = (xs[d] - mean) / stdv;
            sum += -0.5f * z * z - logf(stdv) - HALF_LOG2PI;
        }
        sum += __shfl_xor_sync(0xffffffffu, sum, 1);
        sum += __shfl_xor_sync(0xffffffffu, sum, 2);
        if (part == 0) {
            int n = row;
            g_em[((size_t)t * 8 + b) * 128 + n] = (n < ilen_s) ? sum : 0.f;
            g_tv[((size_t)t * 8 + b) * 128 + n] = pr[160];
        }
    }
}

// ---------------- k_hmm: one warp per batch, shuffle-only ----------------
__global__ __launch_bounds__(32) void k_hmm(
    const int* __restrict__ inputs_len, const int* __restrict__ mel_lens,
    float* __restrict__ out) {
    int b = blockIdx.x, lane = threadIdx.x;
    int ilen = inputs_len[b], mlen = mel_lens[b];
    float la[4];
    float lp = 0.f;
    float* outla = out + 8 + (size_t)b * 256 * 128;
    float emc[4], tvc[4];
#pragma unroll
    for (int q = 0; q < 4; ++q) {
        emc[q] = g_em[(size_t)b * 128 + q * 32 + lane];
        tvc[q] = g_tv[(size_t)b * 128 + q * 32 + lane];
    }
    for (int t = 0; t < T_STEPS; ++t) {
        float emn[4], tvn[4];
        if (t + 1 < T_STEPS) {
#pragma unroll
            for (int q = 0; q < 4; ++q) {
                emn[q] = __ldcg(&g_em[((size_t)(t + 1) * 8 + b) * 128 + q * 32 + lane]);
                tvn[q] = __ldcg(&g_tv[((size_t)(t + 1) * 8 + b) * 128 + q * 32 + lane]);
            }
        }
        float la_t[4];
        if (t == 0) {
#pragma unroll
            for (int q = 0; q < 4; ++q)
                la_t[q] = emc[q] + ((q == 0 && lane == 0) ? 0.f : NEG);
        } else {
            float st_[4], mvv[4];
#pragma unroll
            for (int q = 0; q < 4; ++q) {
                float tv = tvc[q];
                float lstay = logf(fmaxf(1.f / (1.f + expf(tv)), 1e-4f));
                float lmove = logf(fmaxf(1.f / (1.f + expf(-tv)), 1e-4f));
                st_[q] = la[q] + lstay;
                mvv[q] = la[q] + lmove;
            }
            float lv[4];
#pragma unroll
            for (int q = 0; q < 4; ++q)
                lv[q] = __shfl_up_sync(0xffffffffu, mvv[q], 1);
            float c1 = __shfl_sync(0xffffffffu, mvv[0], 31);
            float c2 = __shfl_sync(0xffffffffu, mvv[1], 31);
            float c3 = __shfl_sync(0xffffffffu, mvv[2], 31);
            if (lane == 0) { lv[0] = NEG; lv[1] = c1; lv[2] = c2; lv[3] = c3; }
#pragma unroll
            for (int q = 0; q < 4; ++q) {
                float mx = fmaxf(st_[q], lv[q]);
                float mn = fminf(st_[q], lv[q]);
                float o = mx + log1pf(expf(mn - mx));
                int n = q * 32 + lane;
                o = (n < ilen) ? o : NEG;
                la_t[q] = emc[q] + o;
            }
        }
        float mx = fmaxf(fmaxf(la_t[0], la_t[1]), fmaxf(la_t[2], la_t[3]));
#pragma unroll
        for (int off = 16; off; off >>= 1)
            mx = fmaxf(mx, __shfl_xor_sync(0xffffffffu, mx, off));
        float s = expf(la_t[0] - mx) + expf(la_t[1] - mx) +
                  expf(la_t[2] - mx) + expf(la_t[3] - mx);
#pragma unroll
        for (int off = 16; off; off >>= 1)
            s += __shfl_xor_sync(0xffffffffu, s, off);
        float log_c = mx + logf(s);
#pragma unroll
        for (int q = 0; q < 4; ++q) {
            la[q] = la_t[q] - log_c;
            outla[(size_t)t * 128 + q * 32 + lane] = la[q];
        }
        if (t < mlen) lp += log_c;
#pragma unroll
        for (int q = 0; q < 4; ++q) { emc[q] = emn[q]; tvc[q] = tvn[q]; }
    }
    if (lane == 0) out[b] = lp;
}

// ---------------- launch ----------------
#define GEMM_SMEM (AS_BYTES + 32768)

extern "C" void kernel_launch(void* const* d_in, const int* in_sizes, int n_in,
                              void* d_out, int out_size) {
    const float* inputs = (const float*)d_in[0];
    const float* mels = (const float*)d_in[1];
    const float* pw0 = (const float*)d_in[2];
    const float* pw1 = (const float*)d_in[3];
    const float* wih = (const float*)d_in[4];
    const float* whh = (const float*)d_in[5];
    const float* bih = (const float*)d_in[6];
    const float* bhh = (const float*)d_in[7];
    const float* ow0 = (const float*)d_in[8];
    const float* ob0 = (const float*)d_in[9];
    const float* ow1 = (const float*)d_in[10];
    const float* ob1 = (const float*)d_in[11];
    const float* ow2 = (const float*)d_in[12];
    const float* ob2 = (const float*)d_in[13];
    const int* inputs_len = (const int*)d_in[14];
    const int* mel_lens = (const int*)d_in[15];
    float* out = (float*)d_out;

    cudaFuncSetAttribute(k_big, cudaFuncAttributeMaxDynamicSharedMemorySize, BIG_SMEM);
    cudaFuncSetAttribute(k_gemm, cudaFuncAttributeMaxDynamicSharedMemorySize, GEMM_SMEM);

    float *arwin, *w0p, *pre, *base, *hall, *hpart, *gih, *wihp, *bpp;
    cudaGetSymbolAddress((void**)&arwin, g_arwin);
    cudaGetSymbolAddress((void**)&w0p, g_w0p);
    cudaGetSymbolAddress((void**)&pre, g_pre);
    cudaGetSymbolAddress((void**)&base, g_base);
    cudaGetSymbolAddress((void**)&hall, g_hall);
    cudaGetSymbolAddress((void**)&hpart, g_hpart);
    cudaGetSymbolAddress((void**)&gih, g_gih);
    cudaGetSymbolAddress((void**)&wihp, g_wihp);
    cudaGetSymbolAddress((void**)&bpp, g_bp);

    k_prep<<<256, 256>>>(mels, pw0, ow1, ow2, wih, whh, bih, bhh);
    // p0 = relu(arwin @ w0p^T) -> g_hpart (scratch)
    k_gemm<<<dim3(16, 1), 512, GEMM_SMEM>>>(arwin, 96, 96, w0p, 96, 255, nullptr, nullptr, hpart, 256, 1);
    // pre1 = relu(p0 @ pw1^T) -> g_pre
    k_gemm<<<dim3(16, 1), 512, GEMM_SMEM>>>(hpart, 256, 256, pw1, 256, 255, nullptr, nullptr, pre, 256, 1);
    // gih (PERMUTED cols) = pre1 @ wihp^T + bp
    k_gemm<<<dim3(16, 8), 512, GEMM_SMEM>>>(pre, 256, 256, wihp, 256, 2047, bpp, nullptr, gih, 2048, 0);
    // base = inputs @ ow0[:, :512]^T + ob0
    k_gemm<<<dim3(8, 1), 512, GEMM_SMEM>>>(inputs, 512, 512, ow0, 1024, 255, ob0, nullptr, base, 256, 0);
    // LSTM scan (fp16 MMA, weights in registers)
    k_scan<<<32, 256>>>();
    // hpart = hall @ ow0[:, 512:]^T
    k_gemm<<<dim3(16, 1), 512, GEMM_SMEM>>>(hall, 512, 512, ow0 + 512, 1024, 255, nullptr, nullptr, hpart, 256, 0);
    // fused obs-net + emission (bf16 tensor cores)
    k_big<<<2048, 512, BIG_SMEM>>>(mels, ob1, ob2, inputs_len);
    // HMM forward
    k_hmm<<<8, 32>>>(inputs_len, mel_lens, out);
}